// round 9
// baseline (speedup 1.0000x reference)
#include <cuda_runtime.h>
#include <cuda_fp16.h>
#include <math.h>
#include <stdint.h>

// ================= scratch (device globals) =================
#define NMAX 50000
#define EMAX 400000

__device__ __half g_Q [(size_t)NMAX * 128];
__device__ __half g_Kb[(size_t)NMAX * 128];
__device__ __half g_Vb[(size_t)NMAX * 128];
__device__ __half g_EA[(size_t)EMAX * 128];   // e_attn
__device__ float g_wV [(size_t)NMAX * 128];
__device__ float g_z  [(size_t)NMAX * 8];
// weight images: [n][k] fp16, k padded by 8; 10 slots x 80KB
__device__ char g_wimg[10][81920];

#define SMSB 272  // smem k-stride in bytes (136 fp16)
#define TILEB (128 * SMSB)

// ================= PTX helpers =================
__device__ __forceinline__ uint32_t smem_u32(const void* p) {
    uint32_t a;
    asm("{ .reg .u64 t; cvta.to.shared.u64 t, %1; cvt.u32.u64 %0, t; }" : "=r"(a) : "l"(p));
    return a;
}
__device__ __forceinline__ void cpa16(uint32_t d, const void* s) {
    asm volatile("cp.async.cg.shared.global [%0], [%1], 16;" :: "r"(d), "l"(s));
}
#define CPA_COMMIT() asm volatile("cp.async.commit_group;" ::: "memory")
#define CPA_WAIT(n)  asm volatile("cp.async.wait_group %0;" :: "n"(n) : "memory")

__device__ __forceinline__ void red_add_v2(float* p, float a, float b) {
    asm volatile("red.global.add.v2.f32 [%0], {%1, %2};"
                 :: "l"(p), "f"(a), "f"(b) : "memory");
}
__device__ __forceinline__ void red_add_f(float* p, float a) {
    asm volatile("red.global.add.f32 [%0], %1;" :: "l"(p), "f"(a) : "memory");
}

__device__ __forceinline__ void mma_f16(float* c, const uint32_t* a, const uint32_t* b) {
    asm volatile(
        "mma.sync.aligned.m16n8k16.row.col.f32.f16.f16.f32 "
        "{%0,%1,%2,%3}, {%4,%5,%6,%7}, {%8,%9}, {%0,%1,%2,%3};"
        : "+f"(c[0]), "+f"(c[1]), "+f"(c[2]), "+f"(c[3])
        : "r"(a[0]), "r"(a[1]), "r"(a[2]), "r"(a[3]), "r"(b[0]), "r"(b[1]));
}

// 128x128x128 fp16 tile compute; 8 warps in 2x4; acc accumulates.
__device__ __forceinline__ void compute_tile(float (&acc)[4][4][4],
                                             const char* a_sm, const char* b_sm,
                                             int wm, int wn, int q, int t2) {
#pragma unroll
    for (int ks = 0; ks < 8; ks++) {
        uint32_t av[4][4], bv[4][2];
#pragma unroll
        for (int mt = 0; mt < 4; mt++) {
            int off = (wm * 64 + mt * 16 + q) * SMSB + (ks * 16 + t2) * 2;
            av[mt][0] = *(const uint32_t*)(a_sm + off);
            av[mt][1] = *(const uint32_t*)(a_sm + off + 8 * SMSB);
            av[mt][2] = *(const uint32_t*)(a_sm + off + 16);
            av[mt][3] = *(const uint32_t*)(a_sm + off + 8 * SMSB + 16);
        }
#pragma unroll
        for (int nt = 0; nt < 4; nt++) {
            int off = (wn * 32 + nt * 8 + q) * SMSB + (ks * 16 + t2) * 2;
            bv[nt][0] = *(const uint32_t*)(b_sm + off);
            bv[nt][1] = *(const uint32_t*)(b_sm + off + 16);
        }
#pragma unroll
        for (int mt = 0; mt < 4; mt++)
#pragma unroll
            for (int nt = 0; nt < 4; nt++) mma_f16(acc[mt][nt], av[mt], bv[nt]);
    }
}

// A-load (rows of 128 fp32 -> fp16). ALOAD: 1 LN(P1=g,P2=b), 2 div-by-z(P1=z)
template <int ALOAD>
__device__ __forceinline__ void load_A(const float* __restrict__ A,
                                       const float* __restrict__ P1,
                                       const float* __restrict__ P2,
                                       int M, int m0, char* a_sm, int tid) {
    const int lane = tid & 31;
    float4 gg, bb;
    if (ALOAD == 1) {
        gg = *(const float4*)(P1 + lane * 4);
        bb = *(const float4*)(P2 + lane * 4);
    }
#pragma unroll 4
    for (int i = tid; i < 4096; i += 256) {
        int row = i >> 5;
        float4 v = make_float4(0.f, 0.f, 0.f, 0.f);
        bool valid = (m0 + row < M);
        if (valid) v = *(const float4*)(A + (size_t)(m0 + row) * 128 + lane * 4);
        if (ALOAD == 1) {
            float s = v.x + v.y + v.z + v.w;
#pragma unroll
            for (int o = 16; o; o >>= 1) s += __shfl_xor_sync(0xffffffffu, s, o);
            float mu = s * 0.0078125f;
            float d0 = v.x - mu, d1 = v.y - mu, d2 = v.z - mu, d3 = v.w - mu;
            float qq = d0 * d0 + d1 * d1 + d2 * d2 + d3 * d3;
#pragma unroll
            for (int o = 16; o; o >>= 1) qq += __shfl_xor_sync(0xffffffffu, qq, o);
            float inv = rsqrtf(qq * 0.0078125f + 1e-5f);
            v.x = d0 * inv * gg.x + bb.x;
            v.y = d1 * inv * gg.y + bb.y;
            v.z = d2 * inv * gg.z + bb.z;
            v.w = d3 * inv * gg.w + bb.w;
        } else if (ALOAD == 2) {
            float zz = valid ? P1[(size_t)(m0 + row) * 8 + (lane >> 2)] : 1.0f;
            float inv = 1.0f / (zz + 1e-6f);
            v.x *= inv; v.y *= inv; v.z *= inv; v.w *= inv;
        }
        __half2 p0 = __floats2half2_rn(v.x, v.y);
        __half2 p1 = __floats2half2_rn(v.z, v.w);
        uint2 P;
        P.x = *(const uint32_t*)&p0;
        P.y = *(const uint32_t*)&p1;
        *(uint2*)(a_sm + row * SMSB + lane * 8) = P;
    }
}

// ================= QKV GEMM (K=128): fp16 C = LN(A) @ Wslot =================
__global__ __launch_bounds__(256, 2)
void mma_gemm_ln(const float* __restrict__ A, const float* __restrict__ g,
                 const float* __restrict__ b, const char* __restrict__ BBase,
                 __half* __restrict__ C0, __half* __restrict__ C1,
                 __half* __restrict__ C2, int M) {
    extern __shared__ char smem[];
    char* a_sm = smem;
    char* b_sm = a_sm + TILEB;
    const uint32_t sb_b = smem_u32(smem) + TILEB;

    const int tid = threadIdx.x, wid = tid >> 5, lane = tid & 31;
    const int wm = wid >> 2, wn = wid & 3;
    const int q = lane >> 2, t2 = (lane & 3) * 2;
    const int m0 = blockIdx.x * 128;
    const char* Bg = BBase + (size_t)blockIdx.y * 81920;
    __half* C = (blockIdx.y == 0) ? C0 : (blockIdx.y == 1) ? C1 : C2;

    for (int i = tid * 16; i < TILEB; i += 4096) cpa16(sb_b + i, Bg + i);
    CPA_COMMIT();

    float acc[4][4][4];
#pragma unroll
    for (int mt = 0; mt < 4; mt++)
#pragma unroll
        for (int nt = 0; nt < 4; nt++)
#pragma unroll
            for (int j = 0; j < 4; j++) acc[mt][nt][j] = 0.0f;

    load_A<1>(A, g, b, M, m0, a_sm, tid);
    CPA_WAIT(0);
    __syncthreads();
    compute_tile(acc, a_sm, b_sm, wm, wn, q, t2);

#pragma unroll
    for (int mt = 0; mt < 4; mt++) {
#pragma unroll
        for (int half = 0; half < 2; half++) {
            int row = m0 + wm * 64 + mt * 16 + q + half * 8;
            if (row >= M) continue;
#pragma unroll
            for (int nt = 0; nt < 4; nt++) {
                int col = wn * 32 + nt * 8 + t2;
                __half2 hp = __floats2half2_rn(acc[mt][nt][half * 2 + 0],
                                               acc[mt][nt][half * 2 + 1]);
                *(uint32_t*)((char*)C + ((size_t)row * 128 + col) * 2) =
                    *(const uint32_t*)&hp;
            }
        }
    }
}

// ===== fused PE GEMM + edge attention: PE = LN(edge)@We (in regs); then per edge:
// score = clip(K[src]*Q[dst]/4)*PE -> e_attn; w = exp(clip(head sums));
// wV[dst] += w*V[src]; z[dst] += w  (vector reductions) =====
__global__ __launch_bounds__(256, 2)
void pe_gemm_attn(const float* __restrict__ edgef, const float* __restrict__ g,
                  const float* __restrict__ b, const char* __restrict__ Bimg,
                  const __half* __restrict__ Q, const __half* __restrict__ K,
                  const __half* __restrict__ V, const int* __restrict__ eidx,
                  __half* __restrict__ eattn, float* __restrict__ wV,
                  float* __restrict__ z, int E) {
    extern __shared__ char smem[];
    char* a_sm = smem;
    char* b_sm = a_sm + TILEB;
    int* src_sm = (int*)(smem + 2 * TILEB);
    int* dst_sm = src_sm + 128;
    const uint32_t sb_b = smem_u32(smem) + TILEB;

    const int tid = threadIdx.x, wid = tid >> 5, lane = tid & 31;
    const int wm = wid >> 2, wn = wid & 3;
    const int q = lane >> 2, t2 = (lane & 3) * 2;
    const int m0 = blockIdx.x * 128;

    for (int i = tid * 16; i < TILEB; i += 4096) cpa16(sb_b + i, Bimg + i);
    CPA_COMMIT();

    if (tid < 128) {
        int e = m0 + tid;
        src_sm[tid] = (e < E) ? eidx[e] : 0;
        dst_sm[tid] = (e < E) ? eidx[E + e] : 0;
    }

    float acc[4][4][4];
#pragma unroll
    for (int mt = 0; mt < 4; mt++)
#pragma unroll
        for (int nt = 0; nt < 4; nt++)
#pragma unroll
            for (int j = 0; j < 4; j++) acc[mt][nt][j] = 0.0f;

    load_A<1>(edgef, g, b, E, m0, a_sm, tid);
    CPA_WAIT(0);
    __syncthreads();
    compute_tile(acc, a_sm, b_sm, wm, wn, q, t2);

    // epilogue: per row (edge), head h = 2*wn + (nt>>1); lanes q*4+{0..3} share a row
    const float sc = 0.25f;
#pragma unroll
    for (int mt = 0; mt < 4; mt++) {
#pragma unroll
        for (int half = 0; half < 2; half++) {
            int lrow = wm * 64 + mt * 16 + q + half * 8;
            int e = m0 + lrow;
            bool valid = (e < E);
            int src = src_sm[lrow], dst = dst_sm[lrow];
            float hs0 = 0.0f, hs1 = 0.0f;
            float s_keep[4][2];
#pragma unroll
            for (int nt = 0; nt < 4; nt++) {
                int col = wn * 32 + nt * 8 + t2;
                __half2 kh = *(const __half2*)(K + (size_t)src * 128 + col);
                __half2 qh = *(const __half2*)(Q + (size_t)dst * 128 + col);
                float2 kf = __half22float2(kh), qf = __half22float2(qh);
                float s0 = fminf(fmaxf(kf.x * qf.x * sc, -5.0f), 5.0f) *
                           acc[mt][nt][half * 2 + 0];
                float s1 = fminf(fmaxf(kf.y * qf.y * sc, -5.0f), 5.0f) *
                           acc[mt][nt][half * 2 + 1];
                s_keep[nt][0] = s0;
                s_keep[nt][1] = s1;
                if (nt < 2) hs0 += s0 + s1; else hs1 += s0 + s1;
            }
            // store e_attn
            if (valid) {
#pragma unroll
                for (int nt = 0; nt < 4; nt++) {
                    int col = wn * 32 + nt * 8 + t2;
                    __half2 eh = __floats2half2_rn(s_keep[nt][0], s_keep[nt][1]);
                    *(uint32_t*)((char*)eattn + ((size_t)e * 128 + col) * 2) =
                        *(const uint32_t*)&eh;
                }
            }
            // head sums over the 4 lanes of this q-group (uniform validity in group)
            hs0 += __shfl_xor_sync(0xffffffffu, hs0, 1);
            hs0 += __shfl_xor_sync(0xffffffffu, hs0, 2);
            hs1 += __shfl_xor_sync(0xffffffffu, hs1, 1);
            hs1 += __shfl_xor_sync(0xffffffffu, hs1, 2);
            float w0 = expf(fminf(fmaxf(hs0, -5.0f), 5.0f));
            float w1 = expf(fminf(fmaxf(hs1, -5.0f), 5.0f));
            if (valid) {
#pragma unroll
                for (int nt = 0; nt < 4; nt++) {
                    int col = wn * 32 + nt * 8 + t2;
                    __half2 vh = *(const __half2*)(V + (size_t)src * 128 + col);
                    float2 vf = __half22float2(vh);
                    float w = (nt < 2) ? w0 : w1;
                    red_add_v2(wV + (size_t)dst * 128 + col, vf.x * w, vf.y * w);
                }
                if (t2 == 0) {
                    red_add_f(z + (size_t)dst * 8 + wn * 2 + 0, w0);
                    red_add_f(z + (size_t)dst * 8 + wn * 2 + 1, w1);
                }
            }
        }
    }
}

// ====== merged fused output chain (node + edge sides in one grid) ======
// out = x2 + FFN(LN2(x2)),  x2 = R + bias + op(A)@Wo
__global__ __launch_bounds__(256, 1)
void out_ffn_all(int TtN, int Nn, int Ee, const float* __restrict__ wV,
                 const float* __restrict__ z, const __half* __restrict__ eattn,
                 const char* __restrict__ WoN, const char* __restrict__ WoE,
                 const float* __restrict__ boN, const float* __restrict__ boE,
                 const float* __restrict__ nodeR, const float* __restrict__ edgeR,
                 const char* __restrict__ W1N, const char* __restrict__ W1E,
                 const char* __restrict__ W2N, const char* __restrict__ W2E,
                 const float* __restrict__ gN, const float* __restrict__ bN,
                 const float* __restrict__ gE, const float* __restrict__ bE,
                 float* __restrict__ outBase) {
    extern __shared__ char smem[];
    char* a_sm = smem;
    char* w0 = a_sm + TILEB;
    char* w1 = w0 + TILEB;
    char* t_sm = w1 + TILEB;
    char* x_sm = t_sm + TILEB;
    const uint32_t sb = smem_u32(smem);
    const uint32_t s_w0 = sb + TILEB, s_w1 = s_w0 + TILEB;
    const uint32_t s_x = sb + 4 * TILEB;

    const int tid = threadIdx.x, wid = tid >> 5, lane = tid & 31;
    const int wm = wid >> 2, wn = wid & 3;
    const int q = lane >> 2, t2 = (lane & 3) * 2;

    const bool is_edge = ((int)blockIdx.x >= TtN);
    const int m0 = (is_edge ? (blockIdx.x - TtN) : blockIdx.x) * 128;
    const int M = is_edge ? Ee : Nn;
    const char* Wo = is_edge ? WoE : WoN;
    const float* bias = is_edge ? boE : boN;
    const float* R = is_edge ? edgeR : nodeR;
    const char* W1 = is_edge ? W1E : W1N;
    const char* W2 = is_edge ? W2E : W2N;
    const float* g = is_edge ? gE : gN;
    const float* b = is_edge ? bE : bN;
    float* out = is_edge ? (outBase + (size_t)Nn * 128) : outBase;

    // G0: Wo -> w0, R -> x_sm, (edge: fp16 A -> a_sm)
    for (int i = tid * 16; i < TILEB; i += 4096) cpa16(s_w0 + i, Wo + i);
    for (int i = tid; i < 128 * 32; i += 256) {
        int row = i >> 5, j = i & 31;
        if (m0 + row < M)
            cpa16(s_x + row * 512 + j * 16,
                  (const char*)R + ((size_t)(m0 + row) * 512 + j * 16));
    }
    if (is_edge) {
        for (int i = tid; i < 128 * 16; i += 256) {
            int row = i >> 4, j = i & 15;
            if (m0 + row < M)
                cpa16(sb + row * SMSB + j * 16,
                      (const char*)eattn + (size_t)(m0 + row) * 256 + j * 16);
        }
    }
    CPA_COMMIT();
    // G1: W1 half0 -> w1
    for (int i = tid * 16; i < TILEB; i += 4096) cpa16(s_w1 + i, W1 + i);
    CPA_COMMIT();

    if (!is_edge) load_A<2>(wV, z, nullptr, M, m0, a_sm, tid);

    float acc1[4][4][4];
#pragma unroll
    for (int mt = 0; mt < 4; mt++)
#pragma unroll
        for (int nt = 0; nt < 4; nt++)
#pragma unroll
            for (int j = 0; j < 4; j++) acc1[mt][nt][j] = 0.0f;

    CPA_WAIT(1);  // G0 done
    __syncthreads();
    compute_tile(acc1, a_sm, w0, wm, wn, q, t2);  // op(A) @ Wo
    __syncthreads();
    // G2: W2 chunk0 -> w0
    for (int i = tid; i < 128 * 16; i += 256) {
        int n = i >> 4, j = i & 15;
        cpa16(s_w0 + n * SMSB + j * 16, W2 + (size_t)n * 528 + j * 16);
    }
    CPA_COMMIT();

    // x2 tile into x_sm: x += acc + bias
#pragma unroll
    for (int mt = 0; mt < 4; mt++)
#pragma unroll
        for (int half = 0; half < 2; half++) {
            int lrow = wm * 64 + mt * 16 + q + half * 8;
#pragma unroll
            for (int nt = 0; nt < 4; nt++) {
                int col = wn * 32 + nt * 8 + t2;
                float2 bbv = *(const float2*)(bias + col);
                float2 xx = *(const float2*)(x_sm + lrow * 512 + col * 4);
                xx.x += acc1[mt][nt][half * 2 + 0] + bbv.x;
                xx.y += acc1[mt][nt][half * 2 + 1] + bbv.y;
                *(float2*)(x_sm + lrow * 512 + col * 4) = xx;
            }
        }
    __syncthreads();

    // LN2 over x_sm rows -> a_sm (fp16)
    {
        float4 gg = *(const float4*)(g + lane * 4);
        float4 bb = *(const float4*)(b + lane * 4);
#pragma unroll 4
        for (int i = tid; i < 4096; i += 256) {
            int row = i >> 5;
            float4 v = *(const float4*)(x_sm + row * 512 + lane * 16);
            float s = v.x + v.y + v.z + v.w;
#pragma unroll
            for (int o = 16; o; o >>= 1) s += __shfl_xor_sync(0xffffffffu, s, o);
            float mu = s * 0.0078125f;
            float d0 = v.x - mu, d1 = v.y - mu, d2 = v.z - mu, d3 = v.w - mu;
            float qq = d0 * d0 + d1 * d1 + d2 * d2 + d3 * d3;
#pragma unroll
            for (int o = 16; o; o >>= 1) qq += __shfl_xor_sync(0xffffffffu, qq, o);
            float inv = rsqrtf(qq * 0.0078125f + 1e-5f);
            __half2 p0 = __floats2half2_rn(d0 * inv * gg.x + bb.x, d1 * inv * gg.y + bb.y);
            __half2 p1 = __floats2half2_rn(d2 * inv * gg.z + bb.z, d3 * inv * gg.w + bb.w);
            uint2 P;
            P.x = *(const uint32_t*)&p0;
            P.y = *(const uint32_t*)&p1;
            *(uint2*)(a_sm + row * SMSB + lane * 8) = P;
        }
    }
    __syncthreads();

    float acc2[4][4][4];
#pragma unroll
    for (int mt = 0; mt < 4; mt++)
#pragma unroll
        for (int nt = 0; nt < 4; nt++)
#pragma unroll
            for (int j = 0; j < 4; j++) acc2[mt][nt][j] = 0.0f;

#pragma unroll
    for (int h = 0; h < 2; h++) {
        CPA_WAIT(1);  // h=0: G1 (w1=W1h0); h=1: G3 (w1=W1h1)
        __syncthreads();
#pragma unroll
        for (int mt = 0; mt < 4; mt++)
#pragma unroll
            for (int nt = 0; nt < 4; nt++)
#pragma unroll
                for (int j = 0; j < 4; j++) acc1[mt][nt][j] = 0.0f;
        compute_tile(acc1, a_sm, w1, wm, wn, q, t2);
        __syncthreads();
        if (h == 0) {
            for (int i = tid * 16; i < TILEB; i += 4096) cpa16(s_w1 + i, W1 + TILEB + i);
            CPA_COMMIT();
        }
        // silu -> t_sm (fp16)
#pragma unroll
        for (int mt = 0; mt < 4; mt++)
#pragma unroll
            for (int nt = 0; nt < 4; nt++) {
                int row0 = wm * 64 + mt * 16 + q;
                int col = wn * 32 + nt * 8 + t2;
#pragma unroll
                for (int half = 0; half < 2; half++) {
                    float s0 = acc1[mt][nt][half * 2 + 0];
                    float s1 = acc1[mt][nt][half * 2 + 1];
                    s0 = s0 / (1.0f + expf(-s0));
                    s1 = s1 / (1.0f + expf(-s1));
                    __half2 p = __floats2half2_rn(s0, s1);
                    *(uint32_t*)(t_sm + (row0 + half * 8) * SMSB + col * 2) =
                        *(const uint32_t*)&p;
                }
            }
        if (h == 0) CPA_WAIT(1); else CPA_WAIT(0);  // W2 chunk in w0
        __syncthreads();
        compute_tile(acc2, t_sm, w0, wm, wn, q, t2);
        __syncthreads();
        if (h == 0) {
            for (int i = tid; i < 128 * 16; i += 256) {
                int n = i >> 4, j = i & 15;
                cpa16(s_w0 + n * SMSB + j * 16, W2 + (size_t)n * 528 + 256 + j * 16);
            }
            CPA_COMMIT();
        }
    }

    // epilogue: out = x_sm (x2) + acc2
#pragma unroll
    for (int mt = 0; mt < 4; mt++) {
#pragma unroll
        for (int half = 0; half < 2; half++) {
            int lrow = wm * 64 + mt * 16 + q + half * 8;
            int row = m0 + lrow;
            if (row >= M) continue;
#pragma unroll
            for (int nt = 0; nt < 4; nt++) {
                int col = wn * 32 + nt * 8 + t2;
                float2 rr = *(const float2*)(x_sm + lrow * 512 + col * 4);
                float o0 = acc2[mt][nt][half * 2 + 0] + rr.x;
                float o1 = acc2[mt][nt][half * 2 + 1] + rr.y;
                *(float2*)(out + (size_t)row * 128 + col) = make_float2(o0, o1);
            }
        }
    }
}

// ====== weight prep: all 10 weights, fp16, one launch ======
__global__ void prep_all(const float* w0, const float* w1, const float* w2,
                         const float* w3, const float* w4, const float* w5,
                         const float* w6, const float* w7, const float* w8,
                         const float* w9, char* __restrict__ ib) {
    int y = blockIdx.y;
    const float* W;
    int K = 128, N = 128;
    switch (y) {
        case 0: W = w0; break;
        case 1: W = w1; break;
        case 2: W = w2; break;
        case 3: W = w3; break;
        case 4: W = w4; break;
        case 5: W = w5; break;
        case 6: W = w6; N = 256; break;
        case 7: W = w7; N = 256; break;
        case 8: W = w8; K = 256; break;
        default: W = w9; K = 256; break;
    }
    int idx = blockIdx.x * 256 + threadIdx.x;
    if (idx >= K * N) return;
    int k = idx / N, n = idx % N;
    size_t off = (size_t)y * 81920 + ((size_t)n * (K + 8) + k) * 2;
    *(unsigned short*)(ib + off) = __half_as_ushort(__float2half_rn(W[idx]));
}

__global__ void zero2_kernel(float* __restrict__ a, size_t na,
                             float* __restrict__ bz, size_t nb) {
    size_t i = (size_t)blockIdx.x * blockDim.x + threadIdx.x;
    size_t st = (size_t)gridDim.x * blockDim.x;
    for (size_t k = i; k < na; k += st) a[k] = 0.0f;
    for (size_t k = i; k < nb; k += st) bz[k] = 0.0f;
}

// ================= launch =================
extern "C" void kernel_launch(void* const* d_in, const int* in_sizes, int n_in,
                              void* d_out, int out_size) {
    const float* node = (const float*)d_in[0];
    const float* edge = (const float*)d_in[1];
    const int*   eidx = (const int*)d_in[2];
    const float* Wq = (const float*)d_in[3];
    const float* Wk = (const float*)d_in[4];
    const float* Wv = (const float*)d_in[5];
    const float* We = (const float*)d_in[6];
    const float* Wo_n = (const float*)d_in[7];
    const float* bo_n = (const float*)d_in[8];
    const float* Wo_e = (const float*)d_in[9];
    const float* bo_e = (const float*)d_in[10];
    const float* W1n = (const float*)d_in[11];
    const float* W2n = (const float*)d_in[12];
    const float* W1e = (const float*)d_in[13];
    const float* W2e = (const float*)d_in[14];
    const float* g1n = (const float*)d_in[15];
    const float* b1n = (const float*)d_in[16];
    const float* g1e = (const float*)d_in[17];
    const float* b1e = (const float*)d_in[18];
    const float* g2n = (const float*)d_in[19];
    const float* b2n = (const float*)d_in[20];
    const float* g2e = (const float*)d_in[21];
    const float* b2e = (const float*)d_in[22];

    const int N = in_sizes[0] / 128;
    const int E = in_sizes[1] / 128;
    float* out = (float*)d_out;

    __half *Q, *Kb, *Vb, *EA;
    float *wV, *z;
    char* wim;
    cudaGetSymbolAddress((void**)&Q, g_Q);
    cudaGetSymbolAddress((void**)&Kb, g_Kb);
    cudaGetSymbolAddress((void**)&Vb, g_Vb);
    cudaGetSymbolAddress((void**)&EA, g_EA);
    cudaGetSymbolAddress((void**)&wV, g_wV);
    cudaGetSymbolAddress((void**)&z, g_z);
    cudaGetSymbolAddress((void**)&wim, g_wimg);

    auto IM = [&](int i) { return wim + (size_t)i * 81920; };

    const int SMG = 2 * TILEB;             // 69632
    const int SMP = 2 * TILEB + 1024;      // 70656
    const int SMO = 4 * TILEB + 65536;     // 204800
    cudaFuncSetAttribute((const void*)mma_gemm_ln, cudaFuncAttributeMaxDynamicSharedMemorySize, SMG);
    cudaFuncSetAttribute((const void*)pe_gemm_attn, cudaFuncAttributeMaxDynamicSharedMemorySize, SMP);
    cudaFuncSetAttribute((const void*)out_ffn_all, cudaFuncAttributeMaxDynamicSharedMemorySize, SMO);

    const int TtN = (N + 127) / 128;
    const int TtE = (E + 127) / 128;

    // 0) weight images + accumulator zeroing
    prep_all<<<dim3(128, 10), 256>>>(Wq, Wk, Wv, We, Wo_n, Wo_e, W1n, W1e, W2n, W2e, wim);
    zero2_kernel<<<2048, 256>>>(wV, (size_t)N * 128, z, (size_t)N * 8);

    // 1) fused LN1 + QKV projections (fp16 out; grid.y = slot 0/1/2)
    mma_gemm_ln<<<dim3(TtN, 3), 256, SMG>>>(node, g1n, b1n, IM(0), Q, Kb, Vb, N);

    // 2) fused LN1e + PE GEMM + edge attention + aggregation
    pe_gemm_attn<<<TtE, 256, SMP>>>(edge, g1e, b1e, IM(3), Q, Kb, Vb, eidx,
                                    EA, wV, z, E);

    // 3) merged fused output chains (node tiles first, then edge tiles)
    out_ffn_all<<<TtN + TtE, 256, SMO>>>(TtN, N, E, wV, z, EA,
                                         IM(4), IM(5), bo_n, bo_e, node, edge,
                                         IM(6), IM(7), IM(8), IM(9),
                                         g2n, b2n, g2e, b2e, out);
}

// round 10
// speedup vs baseline: 1.0696x; 1.0696x over previous
#include <cuda_runtime.h>
#include <cuda_fp16.h>
#include <math.h>
#include <stdint.h>

// ================= scratch (device globals) =================
#define NMAX 50000
#define EMAX 400000

__device__ __half g_Q [(size_t)NMAX * 128];
__device__ __half g_Kb[(size_t)NMAX * 128];
__device__ __half g_Vb[(size_t)NMAX * 128];
__device__ __half g_PE[(size_t)EMAX * 128];   // PE -> overwritten with e_attn
__device__ float g_wV [(size_t)NMAX * 128];
__device__ float g_z  [(size_t)NMAX * 8];
// weight images: [n][k] fp16, k padded by 8; 10 slots x 80KB
__device__ char g_wimg[10][81920];

#define SMSB 272  // smem k-stride in bytes (136 fp16)
#define TILEB (128 * SMSB)

// ================= PTX helpers =================
__device__ __forceinline__ uint32_t smem_u32(const void* p) {
    uint32_t a;
    asm("{ .reg .u64 t; cvta.to.shared.u64 t, %1; cvt.u32.u64 %0, t; }" : "=r"(a) : "l"(p));
    return a;
}
__device__ __forceinline__ void cpa16(uint32_t d, const void* s) {
    asm volatile("cp.async.cg.shared.global [%0], [%1], 16;" :: "r"(d), "l"(s));
}
#define CPA_COMMIT() asm volatile("cp.async.commit_group;" ::: "memory")
#define CPA_WAIT(n)  asm volatile("cp.async.wait_group %0;" :: "n"(n) : "memory")

__device__ __forceinline__ void red_add_v4(float* p, float a, float b, float c, float d) {
    asm volatile("red.global.add.v4.f32 [%0], {%1, %2, %3, %4};"
                 :: "l"(p), "f"(a), "f"(b), "f"(c), "f"(d) : "memory");
}
__device__ __forceinline__ void red_add_f(float* p, float a) {
    asm volatile("red.global.add.f32 [%0], %1;" :: "l"(p), "f"(a) : "memory");
}

__device__ __forceinline__ void mma_f16(float* c, const uint32_t* a, const uint32_t* b) {
    asm volatile(
        "mma.sync.aligned.m16n8k16.row.col.f32.f16.f16.f32 "
        "{%0,%1,%2,%3}, {%4,%5,%6,%7}, {%8,%9}, {%0,%1,%2,%3};"
        : "+f"(c[0]), "+f"(c[1]), "+f"(c[2]), "+f"(c[3])
        : "r"(a[0]), "r"(a[1]), "r"(a[2]), "r"(a[3]), "r"(b[0]), "r"(b[1]));
}

// 128x128x128 fp16 tile compute; 8 warps in 2x4; acc accumulates.
__device__ __forceinline__ void compute_tile(float (&acc)[4][4][4],
                                             const char* a_sm, const char* b_sm,
                                             int wm, int wn, int q, int t2) {
#pragma unroll
    for (int ks = 0; ks < 8; ks++) {
        uint32_t av[4][4], bv[4][2];
#pragma unroll
        for (int mt = 0; mt < 4; mt++) {
            int off = (wm * 64 + mt * 16 + q) * SMSB + (ks * 16 + t2) * 2;
            av[mt][0] = *(const uint32_t*)(a_sm + off);
            av[mt][1] = *(const uint32_t*)(a_sm + off + 8 * SMSB);
            av[mt][2] = *(const uint32_t*)(a_sm + off + 16);
            av[mt][3] = *(const uint32_t*)(a_sm + off + 8 * SMSB + 16);
        }
#pragma unroll
        for (int nt = 0; nt < 4; nt++) {
            int off = (wn * 32 + nt * 8 + q) * SMSB + (ks * 16 + t2) * 2;
            bv[nt][0] = *(const uint32_t*)(b_sm + off);
            bv[nt][1] = *(const uint32_t*)(b_sm + off + 16);
        }
#pragma unroll
        for (int mt = 0; mt < 4; mt++)
#pragma unroll
            for (int nt = 0; nt < 4; nt++) mma_f16(acc[mt][nt], av[mt], bv[nt]);
    }
}

// A-load (rows of 128 fp32 -> fp16). ALOAD: 1 LN(P1=g,P2=b), 2 div-by-z(P1=z)
template <int ALOAD>
__device__ __forceinline__ void load_A(const float* __restrict__ A,
                                       const float* __restrict__ P1,
                                       const float* __restrict__ P2,
                                       int M, int m0, char* a_sm, int tid) {
    const int lane = tid & 31;
    float4 gg, bb;
    if (ALOAD == 1) {
        gg = *(const float4*)(P1 + lane * 4);
        bb = *(const float4*)(P2 + lane * 4);
    }
#pragma unroll 4
    for (int i = tid; i < 4096; i += 256) {
        int row = i >> 5;
        float4 v = make_float4(0.f, 0.f, 0.f, 0.f);
        bool valid = (m0 + row < M);
        if (valid) v = *(const float4*)(A + (size_t)(m0 + row) * 128 + lane * 4);
        if (ALOAD == 1) {
            float s = v.x + v.y + v.z + v.w;
#pragma unroll
            for (int o = 16; o; o >>= 1) s += __shfl_xor_sync(0xffffffffu, s, o);
            float mu = s * 0.0078125f;
            float d0 = v.x - mu, d1 = v.y - mu, d2 = v.z - mu, d3 = v.w - mu;
            float qq = d0 * d0 + d1 * d1 + d2 * d2 + d3 * d3;
#pragma unroll
            for (int o = 16; o; o >>= 1) qq += __shfl_xor_sync(0xffffffffu, qq, o);
            float inv = rsqrtf(qq * 0.0078125f + 1e-5f);
            v.x = d0 * inv * gg.x + bb.x;
            v.y = d1 * inv * gg.y + bb.y;
            v.z = d2 * inv * gg.z + bb.z;
            v.w = d3 * inv * gg.w + bb.w;
        } else if (ALOAD == 2) {
            float zz = valid ? P1[(size_t)(m0 + row) * 8 + (lane >> 2)] : 1.0f;
            float inv = 1.0f / (zz + 1e-6f);
            v.x *= inv; v.y *= inv; v.z *= inv; v.w *= inv;
        }
        __half2 p0 = __floats2half2_rn(v.x, v.y);
        __half2 p1 = __floats2half2_rn(v.z, v.w);
        uint2 P;
        P.x = *(const uint32_t*)&p0;
        P.y = *(const uint32_t*)&p1;
        *(uint2*)(a_sm + row * SMSB + lane * 8) = P;
    }
}

// ======= merged projection GEMM: QKV (node, slots 0-2) + PE (edge, slot 3) =======
// 1D grid: [0, 3*TtN) node tiles (slot = bid / TtN), [3*TtN, +TtE) edge tiles.
__global__ __launch_bounds__(256, 2)
void proj_gemm_all(int TtN, const float* __restrict__ nodef,
                   const float* __restrict__ edgef, const float* __restrict__ g1n,
                   const float* __restrict__ b1n, const float* __restrict__ g1e,
                   const float* __restrict__ b1e, const char* __restrict__ WimgBase,
                   __half* __restrict__ Q, __half* __restrict__ Kb,
                   __half* __restrict__ Vb, __half* __restrict__ PE,
                   int Nn, int Ee) {
    extern __shared__ char smem[];
    char* a_sm = smem;
    char* b_sm = a_sm + TILEB;
    const uint32_t sb_b = smem_u32(smem) + TILEB;

    const int tid = threadIdx.x, wid = tid >> 5, lane = tid & 31;
    const int wm = wid >> 2, wn = wid & 3;
    const int q = lane >> 2, t2 = (lane & 3) * 2;

    const int bid = blockIdx.x;
    const bool is_edge = (bid >= 3 * TtN);
    const int slot = is_edge ? 3 : (bid / TtN);
    const int m0 = (is_edge ? (bid - 3 * TtN) : (bid % TtN)) * 128;
    const int M = is_edge ? Ee : Nn;
    const float* A = is_edge ? edgef : nodef;
    const float* g = is_edge ? g1e : g1n;
    const float* b = is_edge ? b1e : b1n;
    __half* C = (slot == 0) ? Q : (slot == 1) ? Kb : (slot == 2) ? Vb : PE;
    const char* Bg = WimgBase + (size_t)slot * 81920;

    for (int i = tid * 16; i < TILEB; i += 4096) cpa16(sb_b + i, Bg + i);
    CPA_COMMIT();

    float acc[4][4][4];
#pragma unroll
    for (int mt = 0; mt < 4; mt++)
#pragma unroll
        for (int nt = 0; nt < 4; nt++)
#pragma unroll
            for (int j = 0; j < 4; j++) acc[mt][nt][j] = 0.0f;

    load_A<1>(A, g, b, M, m0, a_sm, tid);
    CPA_WAIT(0);
    __syncthreads();
    compute_tile(acc, a_sm, b_sm, wm, wn, q, t2);

#pragma unroll
    for (int mt = 0; mt < 4; mt++) {
#pragma unroll
        for (int half = 0; half < 2; half++) {
            int row = m0 + wm * 64 + mt * 16 + q + half * 8;
            if (row >= M) continue;
#pragma unroll
            for (int nt = 0; nt < 4; nt++) {
                int col = wn * 32 + nt * 8 + t2;
                __half2 hp = __floats2half2_rn(acc[mt][nt][half * 2 + 0],
                                               acc[mt][nt][half * 2 + 1]);
                *(uint32_t*)((char*)C + ((size_t)row * 128 + col) * 2) =
                    *(const uint32_t*)&hp;
            }
        }
    }
}

// ================= per-edge attention (one warp per edge, fp16 tensors) =================
__global__ void edge_kernel(const __half* __restrict__ Q, const __half* __restrict__ K,
                            const __half* __restrict__ V, __half* __restrict__ PE,
                            const int* __restrict__ eidx, float* __restrict__ wV,
                            float* __restrict__ z, int E) {
    int e = blockIdx.x * 8 + (threadIdx.x >> 5);
    if (e >= E) return;
    int lane = threadIdx.x & 31;
    int src = eidx[e];
    int dst = eidx[E + e];
    int i = lane * 4;
    uint2 ku = *(const uint2*)(K + (size_t)src * 128 + i);
    uint2 qu = *(const uint2*)(Q + (size_t)dst * 128 + i);
    uint2 pu = *(const uint2*)(PE + (size_t)e * 128 + i);
    float2 k0 = __half22float2(*(__half2*)&ku.x), k1 = __half22float2(*(__half2*)&ku.y);
    float2 q0 = __half22float2(*(__half2*)&qu.x), q1 = __half22float2(*(__half2*)&qu.y);
    float2 p0 = __half22float2(*(__half2*)&pu.x), p1 = __half22float2(*(__half2*)&pu.y);
    const float sc = 0.25f;
    float s0 = fminf(fmaxf(k0.x * q0.x * sc, -5.0f), 5.0f) * p0.x;
    float s1 = fminf(fmaxf(k0.y * q0.y * sc, -5.0f), 5.0f) * p0.y;
    float s2 = fminf(fmaxf(k1.x * q1.x * sc, -5.0f), 5.0f) * p1.x;
    float s3 = fminf(fmaxf(k1.y * q1.y * sc, -5.0f), 5.0f) * p1.y;
    __half2 e0 = __floats2half2_rn(s0, s1), e1 = __floats2half2_rn(s2, s3);
    uint2 eo;
    eo.x = *(const uint32_t*)&e0;
    eo.y = *(const uint32_t*)&e1;
    *(uint2*)(PE + (size_t)e * 128 + i) = eo;

    float hs = s0 + s1 + s2 + s3;
    hs += __shfl_xor_sync(0xffffffffu, hs, 1);
    hs += __shfl_xor_sync(0xffffffffu, hs, 2);
    float w = expf(fminf(fmaxf(hs, -5.0f), 5.0f));

    uint2 vu = *(const uint2*)(V + (size_t)src * 128 + i);
    float2 v0 = __half22float2(*(__half2*)&vu.x), v1 = __half22float2(*(__half2*)&vu.y);
    red_add_v4(wV + (size_t)dst * 128 + i, v0.x * w, v0.y * w, v1.x * w, v1.y * w);
    if ((lane & 3) == 0)
        red_add_f(z + (size_t)dst * 8 + (lane >> 2), w);
}

// ====== merged fused output chain (node + edge sides in one grid) ======
// out = x2 + FFN(LN2(x2)),  x2 = R + bias + op(A)@Wo
__global__ __launch_bounds__(256, 1)
void out_ffn_all(int TtN, int Nn, int Ee, const float* __restrict__ wV,
                 const float* __restrict__ z, const __half* __restrict__ eattn,
                 const char* __restrict__ WoN, const char* __restrict__ WoE,
                 const float* __restrict__ boN, const float* __restrict__ boE,
                 const float* __restrict__ nodeR, const float* __restrict__ edgeR,
                 const char* __restrict__ W1N, const char* __restrict__ W1E,
                 const char* __restrict__ W2N, const char* __restrict__ W2E,
                 const float* __restrict__ gN, const float* __restrict__ bN,
                 const float* __restrict__ gE, const float* __restrict__ bE,
                 float* __restrict__ outBase) {
    extern __shared__ char smem[];
    char* a_sm = smem;
    char* w0 = a_sm + TILEB;
    char* w1 = w0 + TILEB;
    char* t_sm = w1 + TILEB;
    char* x_sm = t_sm + TILEB;
    const uint32_t sb = smem_u32(smem);
    const uint32_t s_w0 = sb + TILEB, s_w1 = s_w0 + TILEB;
    const uint32_t s_x = sb + 4 * TILEB;

    const int tid = threadIdx.x, wid = tid >> 5, lane = tid & 31;
    const int wm = wid >> 2, wn = wid & 3;
    const int q = lane >> 2, t2 = (lane & 3) * 2;

    const bool is_edge = ((int)blockIdx.x >= TtN);
    const int m0 = (is_edge ? (blockIdx.x - TtN) : blockIdx.x) * 128;
    const int M = is_edge ? Ee : Nn;
    const char* Wo = is_edge ? WoE : WoN;
    const float* bias = is_edge ? boE : boN;
    const float* R = is_edge ? edgeR : nodeR;
    const char* W1 = is_edge ? W1E : W1N;
    const char* W2 = is_edge ? W2E : W2N;
    const float* g = is_edge ? gE : gN;
    const float* b = is_edge ? bE : bN;
    float* out = is_edge ? (outBase + (size_t)Nn * 128) : outBase;

    // G0: Wo -> w0, R -> x_sm, (edge: fp16 A -> a_sm)
    for (int i = tid * 16; i < TILEB; i += 4096) cpa16(s_w0 + i, Wo + i);
    for (int i = tid; i < 128 * 32; i += 256) {
        int row = i >> 5, j = i & 31;
        if (m0 + row < M)
            cpa16(s_x + row * 512 + j * 16,
                  (const char*)R + ((size_t)(m0 + row) * 512 + j * 16));
    }
    if (is_edge) {
        for (int i = tid; i < 128 * 16; i += 256) {
            int row = i >> 4, j = i & 15;
            if (m0 + row < M)
                cpa16(sb + row * SMSB + j * 16,
                      (const char*)eattn + (size_t)(m0 + row) * 256 + j * 16);
        }
    }
    CPA_COMMIT();
    // G1: W1 half0 -> w1
    for (int i = tid * 16; i < TILEB; i += 4096) cpa16(s_w1 + i, W1 + i);
    CPA_COMMIT();

    if (!is_edge) load_A<2>(wV, z, nullptr, M, m0, a_sm, tid);

    float acc1[4][4][4];
#pragma unroll
    for (int mt = 0; mt < 4; mt++)
#pragma unroll
        for (int nt = 0; nt < 4; nt++)
#pragma unroll
            for (int j = 0; j < 4; j++) acc1[mt][nt][j] = 0.0f;

    CPA_WAIT(1);  // G0 done
    __syncthreads();
    compute_tile(acc1, a_sm, w0, wm, wn, q, t2);  // op(A) @ Wo
    __syncthreads();
    // G2: W2 chunk0 -> w0
    for (int i = tid; i < 128 * 16; i += 256) {
        int n = i >> 4, j = i & 15;
        cpa16(s_w0 + n * SMSB + j * 16, W2 + (size_t)n * 528 + j * 16);
    }
    CPA_COMMIT();

    // x2 tile into x_sm: x += acc + bias
#pragma unroll
    for (int mt = 0; mt < 4; mt++)
#pragma unroll
        for (int half = 0; half < 2; half++) {
            int lrow = wm * 64 + mt * 16 + q + half * 8;
#pragma unroll
            for (int nt = 0; nt < 4; nt++) {
                int col = wn * 32 + nt * 8 + t2;
                float2 bbv = *(const float2*)(bias + col);
                float2 xx = *(const float2*)(x_sm + lrow * 512 + col * 4);
                xx.x += acc1[mt][nt][half * 2 + 0] + bbv.x;
                xx.y += acc1[mt][nt][half * 2 + 1] + bbv.y;
                *(float2*)(x_sm + lrow * 512 + col * 4) = xx;
            }
        }
    __syncthreads();

    // LN2 over x_sm rows -> a_sm (fp16)
    {
        float4 gg = *(const float4*)(g + lane * 4);
        float4 bb = *(const float4*)(b + lane * 4);
#pragma unroll 4
        for (int i = tid; i < 4096; i += 256) {
            int row = i >> 5;
            float4 v = *(const float4*)(x_sm + row * 512 + lane * 16);
            float s = v.x + v.y + v.z + v.w;
#pragma unroll
            for (int o = 16; o; o >>= 1) s += __shfl_xor_sync(0xffffffffu, s, o);
            float mu = s * 0.0078125f;
            float d0 = v.x - mu, d1 = v.y - mu, d2 = v.z - mu, d3 = v.w - mu;
            float qq = d0 * d0 + d1 * d1 + d2 * d2 + d3 * d3;
#pragma unroll
            for (int o = 16; o; o >>= 1) qq += __shfl_xor_sync(0xffffffffu, qq, o);
            float inv = rsqrtf(qq * 0.0078125f + 1e-5f);
            __half2 p0 = __floats2half2_rn(d0 * inv * gg.x + bb.x, d1 * inv * gg.y + bb.y);
            __half2 p1 = __floats2half2_rn(d2 * inv * gg.z + bb.z, d3 * inv * gg.w + bb.w);
            uint2 P;
            P.x = *(const uint32_t*)&p0;
            P.y = *(const uint32_t*)&p1;
            *(uint2*)(a_sm + row * SMSB + lane * 8) = P;
        }
    }
    __syncthreads();

    float acc2[4][4][4];
#pragma unroll
    for (int mt = 0; mt < 4; mt++)
#pragma unroll
        for (int nt = 0; nt < 4; nt++)
#pragma unroll
            for (int j = 0; j < 4; j++) acc2[mt][nt][j] = 0.0f;

#pragma unroll
    for (int h = 0; h < 2; h++) {
        CPA_WAIT(1);  // h=0: G1 (w1=W1h0); h=1: G3 (w1=W1h1)
        __syncthreads();
#pragma unroll
        for (int mt = 0; mt < 4; mt++)
#pragma unroll
            for (int nt = 0; nt < 4; nt++)
#pragma unroll
                for (int j = 0; j < 4; j++) acc1[mt][nt][j] = 0.0f;
        compute_tile(acc1, a_sm, w1, wm, wn, q, t2);
        __syncthreads();
        if (h == 0) {
            for (int i = tid * 16; i < TILEB; i += 4096) cpa16(s_w1 + i, W1 + TILEB + i);
            CPA_COMMIT();
        }
        // silu -> t_sm (fp16)
#pragma unroll
        for (int mt = 0; mt < 4; mt++)
#pragma unroll
            for (int nt = 0; nt < 4; nt++) {
                int row0 = wm * 64 + mt * 16 + q;
                int col = wn * 32 + nt * 8 + t2;
#pragma unroll
                for (int half = 0; half < 2; half++) {
                    float s0 = acc1[mt][nt][half * 2 + 0];
                    float s1 = acc1[mt][nt][half * 2 + 1];
                    s0 = s0 / (1.0f + expf(-s0));
                    s1 = s1 / (1.0f + expf(-s1));
                    __half2 p = __floats2half2_rn(s0, s1);
                    *(uint32_t*)(t_sm + (row0 + half * 8) * SMSB + col * 2) =
                        *(const uint32_t*)&p;
                }
            }
        if (h == 0) CPA_WAIT(1); else CPA_WAIT(0);  // W2 chunk in w0
        __syncthreads();
        compute_tile(acc2, t_sm, w0, wm, wn, q, t2);
        __syncthreads();
        if (h == 0) {
            for (int i = tid; i < 128 * 16; i += 256) {
                int n = i >> 4, j = i & 15;
                cpa16(s_w0 + n * SMSB + j * 16, W2 + (size_t)n * 528 + 256 + j * 16);
            }
            CPA_COMMIT();
        }
    }

    // epilogue: out = x_sm (x2) + acc2
#pragma unroll
    for (int mt = 0; mt < 4; mt++) {
#pragma unroll
        for (int half = 0; half < 2; half++) {
            int lrow = wm * 64 + mt * 16 + q + half * 8;
            int row = m0 + lrow;
            if (row >= M) continue;
#pragma unroll
            for (int nt = 0; nt < 4; nt++) {
                int col = wn * 32 + nt * 8 + t2;
                float2 rr = *(const float2*)(x_sm + lrow * 512 + col * 4);
                float o0 = acc2[mt][nt][half * 2 + 0] + rr.x;
                float o1 = acc2[mt][nt][half * 2 + 1] + rr.y;
                *(float2*)(out + (size_t)row * 128 + col) = make_float2(o0, o1);
            }
        }
    }
}

// ====== weight prep: all 10 weights, fp16, one launch ======
__global__ void prep_all(const float* w0, const float* w1, const float* w2,
                         const float* w3, const float* w4, const float* w5,
                         const float* w6, const float* w7, const float* w8,
                         const float* w9, char* __restrict__ ib) {
    int y = blockIdx.y;
    const float* W;
    int K = 128, N = 128;
    switch (y) {
        case 0: W = w0; break;
        case 1: W = w1; break;
        case 2: W = w2; break;
        case 3: W = w3; break;
        case 4: W = w4; break;
        case 5: W = w5; break;
        case 6: W = w6; N = 256; break;
        case 7: W = w7; N = 256; break;
        case 8: W = w8; K = 256; break;
        default: W = w9; K = 256; break;
    }
    int idx = blockIdx.x * 256 + threadIdx.x;
    if (idx >= K * N) return;
    int k = idx / N, n = idx % N;
    size_t off = (size_t)y * 81920 + ((size_t)n * (K + 8) + k) * 2;
    *(unsigned short*)(ib + off) = __half_as_ushort(__float2half_rn(W[idx]));
}

__global__ void zero2_kernel(float* __restrict__ a, size_t na,
                             float* __restrict__ bz, size_t nb) {
    size_t i = (size_t)blockIdx.x * blockDim.x + threadIdx.x;
    size_t st = (size_t)gridDim.x * blockDim.x;
    for (size_t k = i; k < na; k += st) a[k] = 0.0f;
    for (size_t k = i; k < nb; k += st) bz[k] = 0.0f;
}

// ================= launch =================
extern "C" void kernel_launch(void* const* d_in, const int* in_sizes, int n_in,
                              void* d_out, int out_size) {
    const float* node = (const float*)d_in[0];
    const float* edge = (const float*)d_in[1];
    const int*   eidx = (const int*)d_in[2];
    const float* Wq = (const float*)d_in[3];
    const float* Wk = (const float*)d_in[4];
    const float* Wv = (const float*)d_in[5];
    const float* We = (const float*)d_in[6];
    const float* Wo_n = (const float*)d_in[7];
    const float* bo_n = (const float*)d_in[8];
    const float* Wo_e = (const float*)d_in[9];
    const float* bo_e = (const float*)d_in[10];
    const float* W1n = (const float*)d_in[11];
    const float* W2n = (const float*)d_in[12];
    const float* W1e = (const float*)d_in[13];
    const float* W2e = (const float*)d_in[14];
    const float* g1n = (const float*)d_in[15];
    const float* b1n = (const float*)d_in[16];
    const float* g1e = (const float*)d_in[17];
    const float* b1e = (const float*)d_in[18];
    const float* g2n = (const float*)d_in[19];
    const float* b2n = (const float*)d_in[20];
    const float* g2e = (const float*)d_in[21];
    const float* b2e = (const float*)d_in[22];

    const int N = in_sizes[0] / 128;
    const int E = in_sizes[1] / 128;
    float* out = (float*)d_out;

    __half *Q, *Kb, *Vb, *PE;
    float *wV, *z;
    char* wim;
    cudaGetSymbolAddress((void**)&Q, g_Q);
    cudaGetSymbolAddress((void**)&Kb, g_Kb);
    cudaGetSymbolAddress((void**)&Vb, g_Vb);
    cudaGetSymbolAddress((void**)&PE, g_PE);
    cudaGetSymbolAddress((void**)&wV, g_wV);
    cudaGetSymbolAddress((void**)&z, g_z);
    cudaGetSymbolAddress((void**)&wim, g_wimg);

    auto IM = [&](int i) { return wim + (size_t)i * 81920; };

    const int SMG = 2 * TILEB;             // 69632
    const int SMO = 4 * TILEB + 65536;     // 204800
    cudaFuncSetAttribute((const void*)proj_gemm_all, cudaFuncAttributeMaxDynamicSharedMemorySize, SMG);
    cudaFuncSetAttribute((const void*)out_ffn_all, cudaFuncAttributeMaxDynamicSharedMemorySize, SMO);

    const int TtN = (N + 127) / 128;
    const int TtE = (E + 127) / 128;

    // 0) weight images + accumulator zeroing
    prep_all<<<dim3(128, 10), 256>>>(Wq, Wk, Wv, We, Wo_n, Wo_e, W1n, W1e, W2n, W2e, wim);
    zero2_kernel<<<2048, 256>>>(wV, (size_t)N * 128, z, (size_t)N * 8);

    // 1) merged projections: LN1+QKV (node) and LN1e+PE (edge) in one launch
    proj_gemm_all<<<3 * TtN + TtE, 256, SMG>>>(TtN, node, edge, g1n, b1n, g1e, b1e,
                                               IM(0), Q, Kb, Vb, PE, N, E);

    // 2) per-edge attention + aggregation (warp-per-edge, coalesced)
    edge_kernel<<<(E + 7) / 8, 256>>>(Q, Kb, Vb, PE, eidx, wV, z, E);

    // 3) merged fused output chains (node tiles first, then edge tiles)
    out_ffn_all<<<TtN + TtE, 256, SMO>>>(TtN, N, E, wV, z, PE,
                                         IM(4), IM(5), bo_n, bo_e, node, edge,
                                         IM(6), IM(7), IM(8), IM(9),
                                         g2n, b2n, g2e, b2e, out);
}

// round 11
// speedup vs baseline: 1.2024x; 1.1241x over previous
#include <cuda_runtime.h>
#include <cuda_fp16.h>
#include <math.h>
#include <stdint.h>

// ================= scratch (device globals) =================
#define NMAX 50000
#define EMAX 400000

__device__ __half g_Q [(size_t)NMAX * 128];
__device__ __half g_Kb[(size_t)NMAX * 128];
__device__ __half g_Vb[(size_t)NMAX * 128];
__device__ __half g_PE[(size_t)EMAX * 128];   // PE -> overwritten with e_attn
__device__ float g_wV [(size_t)NMAX * 128];
__device__ float g_z  [(size_t)NMAX * 8];
// weight images: [n][k] fp16, k padded by 8; 10 slots x 80KB
__device__ char g_wimg[10][81920];

#define SMSB 272  // smem k-stride in bytes (136 fp16)
#define TILEB (128 * SMSB)

// ================= PTX helpers =================
__device__ __forceinline__ uint32_t smem_u32(const void* p) {
    uint32_t a;
    asm("{ .reg .u64 t; cvta.to.shared.u64 t, %1; cvt.u32.u64 %0, t; }" : "=r"(a) : "l"(p));
    return a;
}
__device__ __forceinline__ void cpa16(uint32_t d, const void* s) {
    asm volatile("cp.async.cg.shared.global [%0], [%1], 16;" :: "r"(d), "l"(s));
}
#define CPA_COMMIT() asm volatile("cp.async.commit_group;" ::: "memory")
#define CPA_WAIT(n)  asm volatile("cp.async.wait_group %0;" :: "n"(n) : "memory")

__device__ __forceinline__ void red_add_v4(float* p, float a, float b, float c, float d) {
    asm volatile("red.global.add.v4.f32 [%0], {%1, %2, %3, %4};"
                 :: "l"(p), "f"(a), "f"(b), "f"(c), "f"(d) : "memory");
}
__device__ __forceinline__ void red_add_f(float* p, float a) {
    asm volatile("red.global.add.f32 [%0], %1;" :: "l"(p), "f"(a) : "memory");
}

__device__ __forceinline__ void mma_f16(float* c, const uint32_t* a, const uint32_t* b) {
    asm volatile(
        "mma.sync.aligned.m16n8k16.row.col.f32.f16.f16.f32 "
        "{%0,%1,%2,%3}, {%4,%5,%6,%7}, {%8,%9}, {%0,%1,%2,%3};"
        : "+f"(c[0]), "+f"(c[1]), "+f"(c[2]), "+f"(c[3])
        : "r"(a[0]), "r"(a[1]), "r"(a[2]), "r"(a[3]), "r"(b[0]), "r"(b[1]));
}

// 128x128x128 fp16 tile compute; 8 warps in 2x4 (warp tile 64x32); acc accumulates.
__device__ __forceinline__ void compute_tile(float (&acc)[4][4][4],
                                             const char* a_sm, const char* b_sm,
                                             int wm, int wn, int q, int t2) {
#pragma unroll
    for (int ks = 0; ks < 8; ks++) {
        uint32_t av[4][4], bv[4][2];
#pragma unroll
        for (int mt = 0; mt < 4; mt++) {
            int off = (wm * 64 + mt * 16 + q) * SMSB + (ks * 16 + t2) * 2;
            av[mt][0] = *(const uint32_t*)(a_sm + off);
            av[mt][1] = *(const uint32_t*)(a_sm + off + 8 * SMSB);
            av[mt][2] = *(const uint32_t*)(a_sm + off + 16);
            av[mt][3] = *(const uint32_t*)(a_sm + off + 8 * SMSB + 16);
        }
#pragma unroll
        for (int nt = 0; nt < 4; nt++) {
            int off = (wn * 32 + nt * 8 + q) * SMSB + (ks * 16 + t2) * 2;
            bv[nt][0] = *(const uint32_t*)(b_sm + off);
            bv[nt][1] = *(const uint32_t*)(b_sm + off + 16);
        }
#pragma unroll
        for (int mt = 0; mt < 4; mt++)
#pragma unroll
            for (int nt = 0; nt < 4; nt++) mma_f16(acc[mt][nt], av[mt], bv[nt]);
    }
}

// 128x128x128 fp16 tile compute; 16 warps in 4x4 (warp tile 32x32); acc accumulates.
__device__ __forceinline__ void compute_tile16(float (&acc)[2][4][4],
                                               const char* a_sm, const char* b_sm,
                                               int wm, int wn, int q, int t2) {
#pragma unroll
    for (int ks = 0; ks < 8; ks++) {
        uint32_t av[2][4], bv[4][2];
#pragma unroll
        for (int mt = 0; mt < 2; mt++) {
            int off = (wm * 32 + mt * 16 + q) * SMSB + (ks * 16 + t2) * 2;
            av[mt][0] = *(const uint32_t*)(a_sm + off);
            av[mt][1] = *(const uint32_t*)(a_sm + off + 8 * SMSB);
            av[mt][2] = *(const uint32_t*)(a_sm + off + 16);
            av[mt][3] = *(const uint32_t*)(a_sm + off + 8 * SMSB + 16);
        }
#pragma unroll
        for (int nt = 0; nt < 4; nt++) {
            int off = (wn * 32 + nt * 8 + q) * SMSB + (ks * 16 + t2) * 2;
            bv[nt][0] = *(const uint32_t*)(b_sm + off);
            bv[nt][1] = *(const uint32_t*)(b_sm + off + 16);
        }
#pragma unroll
        for (int mt = 0; mt < 2; mt++)
#pragma unroll
            for (int nt = 0; nt < 4; nt++) mma_f16(acc[mt][nt], av[mt], bv[nt]);
    }
}

// A-load (rows of 128 fp32 -> fp16). ALOAD: 1 LN(P1=g,P2=b), 2 div-by-z(P1=z)
// NT = thread count (256 or 512)
template <int ALOAD, int NT>
__device__ __forceinline__ void load_A(const float* __restrict__ A,
                                       const float* __restrict__ P1,
                                       const float* __restrict__ P2,
                                       int M, int m0, char* a_sm, int tid) {
    const int lane = tid & 31;
    float4 gg, bb;
    if (ALOAD == 1) {
        gg = *(const float4*)(P1 + lane * 4);
        bb = *(const float4*)(P2 + lane * 4);
    }
#pragma unroll 4
    for (int i = tid; i < 4096; i += NT) {
        int row = i >> 5;
        float4 v = make_float4(0.f, 0.f, 0.f, 0.f);
        bool valid = (m0 + row < M);
        if (valid) v = *(const float4*)(A + (size_t)(m0 + row) * 128 + lane * 4);
        if (ALOAD == 1) {
            float s = v.x + v.y + v.z + v.w;
#pragma unroll
            for (int o = 16; o; o >>= 1) s += __shfl_xor_sync(0xffffffffu, s, o);
            float mu = s * 0.0078125f;
            float d0 = v.x - mu, d1 = v.y - mu, d2 = v.z - mu, d3 = v.w - mu;
            float qq = d0 * d0 + d1 * d1 + d2 * d2 + d3 * d3;
#pragma unroll
            for (int o = 16; o; o >>= 1) qq += __shfl_xor_sync(0xffffffffu, qq, o);
            float inv = rsqrtf(qq * 0.0078125f + 1e-5f);
            v.x = d0 * inv * gg.x + bb.x;
            v.y = d1 * inv * gg.y + bb.y;
            v.z = d2 * inv * gg.z + bb.z;
            v.w = d3 * inv * gg.w + bb.w;
        } else if (ALOAD == 2) {
            float zz = valid ? P1[(size_t)(m0 + row) * 8 + (lane >> 2)] : 1.0f;
            float inv = 1.0f / (zz + 1e-6f);
            v.x *= inv; v.y *= inv; v.z *= inv; v.w *= inv;
        }
        __half2 p0 = __floats2half2_rn(v.x, v.y);
        __half2 p1 = __floats2half2_rn(v.z, v.w);
        uint2 P;
        P.x = *(const uint32_t*)&p0;
        P.y = *(const uint32_t*)&p1;
        *(uint2*)(a_sm + row * SMSB + lane * 8) = P;
    }
}

// ======= merged projection GEMM: QKV (node, slots 0-2) + PE (edge, slot 3) =======
__global__ __launch_bounds__(256, 2)
void proj_gemm_all(int TtN, const float* __restrict__ nodef,
                   const float* __restrict__ edgef, const float* __restrict__ g1n,
                   const float* __restrict__ b1n, const float* __restrict__ g1e,
                   const float* __restrict__ b1e, const char* __restrict__ WimgBase,
                   __half* __restrict__ Q, __half* __restrict__ Kb,
                   __half* __restrict__ Vb, __half* __restrict__ PE,
                   int Nn, int Ee) {
    extern __shared__ char smem[];
    char* a_sm = smem;
    char* b_sm = a_sm + TILEB;
    const uint32_t sb_b = smem_u32(smem) + TILEB;

    const int tid = threadIdx.x, wid = tid >> 5, lane = tid & 31;
    const int wm = wid >> 2, wn = wid & 3;
    const int q = lane >> 2, t2 = (lane & 3) * 2;

    const int bid = blockIdx.x;
    const bool is_edge = (bid >= 3 * TtN);
    const int slot = is_edge ? 3 : (bid / TtN);
    const int m0 = (is_edge ? (bid - 3 * TtN) : (bid % TtN)) * 128;
    const int M = is_edge ? Ee : Nn;
    const float* A = is_edge ? edgef : nodef;
    const float* g = is_edge ? g1e : g1n;
    const float* b = is_edge ? b1e : b1n;
    __half* C = (slot == 0) ? Q : (slot == 1) ? Kb : (slot == 2) ? Vb : PE;
    const char* Bg = WimgBase + (size_t)slot * 81920;

    for (int i = tid * 16; i < TILEB; i += 4096) cpa16(sb_b + i, Bg + i);
    CPA_COMMIT();

    float acc[4][4][4];
#pragma unroll
    for (int mt = 0; mt < 4; mt++)
#pragma unroll
        for (int nt = 0; nt < 4; nt++)
#pragma unroll
            for (int j = 0; j < 4; j++) acc[mt][nt][j] = 0.0f;

    load_A<1, 256>(A, g, b, M, m0, a_sm, tid);
    CPA_WAIT(0);
    __syncthreads();
    compute_tile(acc, a_sm, b_sm, wm, wn, q, t2);

#pragma unroll
    for (int mt = 0; mt < 4; mt++) {
#pragma unroll
        for (int half = 0; half < 2; half++) {
            int row = m0 + wm * 64 + mt * 16 + q + half * 8;
            if (row >= M) continue;
#pragma unroll
            for (int nt = 0; nt < 4; nt++) {
                int col = wn * 32 + nt * 8 + t2;
                __half2 hp = __floats2half2_rn(acc[mt][nt][half * 2 + 0],
                                               acc[mt][nt][half * 2 + 1]);
                *(uint32_t*)((char*)C + ((size_t)row * 128 + col) * 2) =
                    *(const uint32_t*)&hp;
            }
        }
    }
}

// ================= per-edge attention (one warp per edge, fp16 tensors) =================
__global__ void edge_kernel(const __half* __restrict__ Q, const __half* __restrict__ K,
                            const __half* __restrict__ V, __half* __restrict__ PE,
                            const int* __restrict__ eidx, float* __restrict__ wV,
                            float* __restrict__ z, int E) {
    int e = blockIdx.x * 8 + (threadIdx.x >> 5);
    if (e >= E) return;
    int lane = threadIdx.x & 31;
    int src = eidx[e];
    int dst = eidx[E + e];
    int i = lane * 4;
    uint2 ku = *(const uint2*)(K + (size_t)src * 128 + i);
    uint2 qu = *(const uint2*)(Q + (size_t)dst * 128 + i);
    uint2 pu = *(const uint2*)(PE + (size_t)e * 128 + i);
    float2 k0 = __half22float2(*(__half2*)&ku.x), k1 = __half22float2(*(__half2*)&ku.y);
    float2 q0 = __half22float2(*(__half2*)&qu.x), q1 = __half22float2(*(__half2*)&qu.y);
    float2 p0 = __half22float2(*(__half2*)&pu.x), p1 = __half22float2(*(__half2*)&pu.y);
    const float sc = 0.25f;
    float s0 = fminf(fmaxf(k0.x * q0.x * sc, -5.0f), 5.0f) * p0.x;
    float s1 = fminf(fmaxf(k0.y * q0.y * sc, -5.0f), 5.0f) * p0.y;
    float s2 = fminf(fmaxf(k1.x * q1.x * sc, -5.0f), 5.0f) * p1.x;
    float s3 = fminf(fmaxf(k1.y * q1.y * sc, -5.0f), 5.0f) * p1.y;
    __half2 e0 = __floats2half2_rn(s0, s1), e1 = __floats2half2_rn(s2, s3);
    uint2 eo;
    eo.x = *(const uint32_t*)&e0;
    eo.y = *(const uint32_t*)&e1;
    *(uint2*)(PE + (size_t)e * 128 + i) = eo;

    float hs = s0 + s1 + s2 + s3;
    hs += __shfl_xor_sync(0xffffffffu, hs, 1);
    hs += __shfl_xor_sync(0xffffffffu, hs, 2);
    float w = expf(fminf(fmaxf(hs, -5.0f), 5.0f));

    uint2 vu = *(const uint2*)(V + (size_t)src * 128 + i);
    float2 v0 = __half22float2(*(__half2*)&vu.x), v1 = __half22float2(*(__half2*)&vu.y);
    red_add_v4(wV + (size_t)dst * 128 + i, v0.x * w, v0.y * w, v1.x * w, v1.y * w);
    if ((lane & 3) == 0)
        red_add_f(z + (size_t)dst * 8 + (lane >> 2), w);
}

// ====== merged fused output chain (node + edge, one grid), 512 threads ======
// out = x2 + FFN(LN2(x2)),  x2 = R + bias + op(A)@Wo
__global__ __launch_bounds__(512, 1)
void out_ffn_all(int TtN, int Nn, int Ee, const float* __restrict__ wV,
                 const float* __restrict__ z, const __half* __restrict__ eattn,
                 const char* __restrict__ WoN, const char* __restrict__ WoE,
                 const float* __restrict__ boN, const float* __restrict__ boE,
                 const float* __restrict__ nodeR, const float* __restrict__ edgeR,
                 const char* __restrict__ W1N, const char* __restrict__ W1E,
                 const char* __restrict__ W2N, const char* __restrict__ W2E,
                 const float* __restrict__ gN, const float* __restrict__ bN,
                 const float* __restrict__ gE, const float* __restrict__ bE,
                 float* __restrict__ outBase) {
    extern __shared__ char smem[];
    char* a_sm = smem;
    char* w0 = a_sm + TILEB;
    char* w1 = w0 + TILEB;
    char* t_sm = w1 + TILEB;
    char* x_sm = t_sm + TILEB;
    const uint32_t sb = smem_u32(smem);
    const uint32_t s_w0 = sb + TILEB, s_w1 = s_w0 + TILEB;
    const uint32_t s_x = sb + 4 * TILEB;

    const int tid = threadIdx.x, wid = tid >> 5, lane = tid & 31;
    const int wm = wid >> 2, wn = wid & 3;   // 4x4 warp grid, warp tile 32x32
    const int q = lane >> 2, t2 = (lane & 3) * 2;

    const bool is_edge = ((int)blockIdx.x >= TtN);
    const int m0 = (is_edge ? (blockIdx.x - TtN) : blockIdx.x) * 128;
    const int M = is_edge ? Ee : Nn;
    const char* Wo = is_edge ? WoE : WoN;
    const float* bias = is_edge ? boE : boN;
    const float* R = is_edge ? edgeR : nodeR;
    const char* W1 = is_edge ? W1E : W1N;
    const char* W2 = is_edge ? W2E : W2N;
    const float* g = is_edge ? gE : gN;
    const float* b = is_edge ? bE : bN;
    float* out = is_edge ? (outBase + (size_t)Nn * 128) : outBase;

    // G0: Wo -> w0, R -> x_sm, (edge: fp16 A -> a_sm)
    for (int i = tid * 16; i < TILEB; i += 8192) cpa16(s_w0 + i, Wo + i);
    for (int i = tid; i < 128 * 32; i += 512) {
        int row = i >> 5, j = i & 31;
        if (m0 + row < M)
            cpa16(s_x + row * 512 + j * 16,
                  (const char*)R + ((size_t)(m0 + row) * 512 + j * 16));
    }
    if (is_edge) {
        for (int i = tid; i < 128 * 16; i += 512) {
            int row = i >> 4, j = i & 15;
            if (m0 + row < M)
                cpa16(sb + row * SMSB + j * 16,
                      (const char*)eattn + (size_t)(m0 + row) * 256 + j * 16);
        }
    }
    CPA_COMMIT();
    // G1: W1 half0 -> w1
    for (int i = tid * 16; i < TILEB; i += 8192) cpa16(s_w1 + i, W1 + i);
    CPA_COMMIT();

    if (!is_edge) load_A<2, 512>(wV, z, nullptr, M, m0, a_sm, tid);

    float acc1[2][4][4];
#pragma unroll
    for (int mt = 0; mt < 2; mt++)
#pragma unroll
        for (int nt = 0; nt < 4; nt++)
#pragma unroll
            for (int j = 0; j < 4; j++) acc1[mt][nt][j] = 0.0f;

    CPA_WAIT(1);  // G0 done
    __syncthreads();
    compute_tile16(acc1, a_sm, w0, wm, wn, q, t2);  // op(A) @ Wo
    __syncthreads();
    // G2: W2 chunk0 -> w0
    for (int i = tid; i < 128 * 16; i += 512) {
        int n = i >> 4, j = i & 15;
        cpa16(s_w0 + n * SMSB + j * 16, W2 + (size_t)n * 528 + j * 16);
    }
    CPA_COMMIT();

    // x2 tile into x_sm: x += acc + bias
#pragma unroll
    for (int mt = 0; mt < 2; mt++)
#pragma unroll
        for (int half = 0; half < 2; half++) {
            int lrow = wm * 32 + mt * 16 + q + half * 8;
#pragma unroll
            for (int nt = 0; nt < 4; nt++) {
                int col = wn * 32 + nt * 8 + t2;
                float2 bbv = *(const float2*)(bias + col);
                float2 xx = *(const float2*)(x_sm + lrow * 512 + col * 4);
                xx.x += acc1[mt][nt][half * 2 + 0] + bbv.x;
                xx.y += acc1[mt][nt][half * 2 + 1] + bbv.y;
                *(float2*)(x_sm + lrow * 512 + col * 4) = xx;
            }
        }
    __syncthreads();

    // LN2 over x_sm rows -> a_sm (fp16)
    {
        float4 gg = *(const float4*)(g + lane * 4);
        float4 bb = *(const float4*)(b + lane * 4);
#pragma unroll 4
        for (int i = tid; i < 4096; i += 512) {
            int row = i >> 5;
            float4 v = *(const float4*)(x_sm + row * 512 + lane * 16);
            float s = v.x + v.y + v.z + v.w;
#pragma unroll
            for (int o = 16; o; o >>= 1) s += __shfl_xor_sync(0xffffffffu, s, o);
            float mu = s * 0.0078125f;
            float d0 = v.x - mu, d1 = v.y - mu, d2 = v.z - mu, d3 = v.w - mu;
            float qq = d0 * d0 + d1 * d1 + d2 * d2 + d3 * d3;
#pragma unroll
            for (int o = 16; o; o >>= 1) qq += __shfl_xor_sync(0xffffffffu, qq, o);
            float inv = rsqrtf(qq * 0.0078125f + 1e-5f);
            __half2 p0 = __floats2half2_rn(d0 * inv * gg.x + bb.x, d1 * inv * gg.y + bb.y);
            __half2 p1 = __floats2half2_rn(d2 * inv * gg.z + bb.z, d3 * inv * gg.w + bb.w);
            uint2 P;
            P.x = *(const uint32_t*)&p0;
            P.y = *(const uint32_t*)&p1;
            *(uint2*)(a_sm + row * SMSB + lane * 8) = P;
        }
    }
    __syncthreads();

    float acc2[2][4][4];
#pragma unroll
    for (int mt = 0; mt < 2; mt++)
#pragma unroll
        for (int nt = 0; nt < 4; nt++)
#pragma unroll
            for (int j = 0; j < 4; j++) acc2[mt][nt][j] = 0.0f;

#pragma unroll
    for (int h = 0; h < 2; h++) {
        CPA_WAIT(1);  // h=0: G1 (w1=W1h0); h=1: G3 (w1=W1h1)
        __syncthreads();
#pragma unroll
        for (int mt = 0; mt < 2; mt++)
#pragma unroll
            for (int nt = 0; nt < 4; nt++)
#pragma unroll
                for (int j = 0; j < 4; j++) acc1[mt][nt][j] = 0.0f;
        compute_tile16(acc1, a_sm, w1, wm, wn, q, t2);
        __syncthreads();
        if (h == 0) {
            for (int i = tid * 16; i < TILEB; i += 8192) cpa16(s_w1 + i, W1 + TILEB + i);
            CPA_COMMIT();
        }
        // silu -> t_sm (fp16)
#pragma unroll
        for (int mt = 0; mt < 2; mt++)
#pragma unroll
            for (int nt = 0; nt < 4; nt++) {
                int row0 = wm * 32 + mt * 16 + q;
                int col = wn * 32 + nt * 8 + t2;
#pragma unroll
                for (int half = 0; half < 2; half++) {
                    float s0 = acc1[mt][nt][half * 2 + 0];
                    float s1 = acc1[mt][nt][half * 2 + 1];
                    s0 = s0 / (1.0f + expf(-s0));
                    s1 = s1 / (1.0f + expf(-s1));
                    __half2 p = __floats2half2_rn(s0, s1);
                    *(uint32_t*)(t_sm + (row0 + half * 8) * SMSB + col * 2) =
                        *(const uint32_t*)&p;
                }
            }
        if (h == 0) CPA_WAIT(1); else CPA_WAIT(0);  // W2 chunk in w0
        __syncthreads();
        compute_tile16(acc2, t_sm, w0, wm, wn, q, t2);
        __syncthreads();
        if (h == 0) {
            for (int i = tid; i < 128 * 16; i += 512) {
                int n = i >> 4, j = i & 15;
                cpa16(s_w0 + n * SMSB + j * 16, W2 + (size_t)n * 528 + 256 + j * 16);
            }
            CPA_COMMIT();
        }
    }

    // epilogue: out = x_sm (x2) + acc2
#pragma unroll
    for (int mt = 0; mt < 2; mt++) {
#pragma unroll
        for (int half = 0; half < 2; half++) {
            int lrow = wm * 32 + mt * 16 + q + half * 8;
            int row = m0 + lrow;
            if (row >= M) continue;
#pragma unroll
            for (int nt = 0; nt < 4; nt++) {
                int col = wn * 32 + nt * 8 + t2;
                float2 rr = *(const float2*)(x_sm + lrow * 512 + col * 4);
                float o0 = acc2[mt][nt][half * 2 + 0] + rr.x;
                float o1 = acc2[mt][nt][half * 2 + 1] + rr.y;
                *(float2*)(out + (size_t)row * 128 + col) = make_float2(o0, o1);
            }
        }
    }
}

// ====== weight prep: all 10 weights, fp16, one launch ======
__global__ void prep_all(const float* w0, const float* w1, const float* w2,
                         const float* w3, const float* w4, const float* w5,
                         const float* w6, const float* w7, const float* w8,
                         const float* w9, char* __restrict__ ib) {
    int y = blockIdx.y;
    const float* W;
    int K = 128, N = 128;
    switch (y) {
        case 0: W = w0; break;
        case 1: W = w1; break;
        case 2: W = w2; break;
        case 3: W = w3; break;
        case 4: W = w4; break;
        case 5: W = w5; break;
        case 6: W = w6; N = 256; break;
        case 7: W = w7; N = 256; break;
        case 8: W = w8; K = 256; break;
        default: W = w9; K = 256; break;
    }
    int idx = blockIdx.x * 256 + threadIdx.x;
    if (idx >= K * N) return;
    int k = idx / N, n = idx % N;
    size_t off = (size_t)y * 81920 + ((size_t)n * (K + 8) + k) * 2;
    *(unsigned short*)(ib + off) = __half_as_ushort(__float2half_rn(W[idx]));
}

__global__ void zero2_kernel(float* __restrict__ a, size_t na,
                             float* __restrict__ bz, size_t nb) {
    size_t i = (size_t)blockIdx.x * blockDim.x + threadIdx.x;
    size_t st = (size_t)gridDim.x * blockDim.x;
    for (size_t k = i; k < na; k += st) a[k] = 0.0f;
    for (size_t k = i; k < nb; k += st) bz[k] = 0.0f;
}

// ================= launch =================
extern "C" void kernel_launch(void* const* d_in, const int* in_sizes, int n_in,
                              void* d_out, int out_size) {
    const float* node = (const float*)d_in[0];
    const float* edge = (const float*)d_in[1];
    const int*   eidx = (const int*)d_in[2];
    const float* Wq = (const float*)d_in[3];
    const float* Wk = (const float*)d_in[4];
    const float* Wv = (const float*)d_in[5];
    const float* We = (const float*)d_in[6];
    const float* Wo_n = (const float*)d_in[7];
    const float* bo_n = (const float*)d_in[8];
    const float* Wo_e = (const float*)d_in[9];
    const float* bo_e = (const float*)d_in[10];
    const float* W1n = (const float*)d_in[11];
    const float* W2n = (const float*)d_in[12];
    const float* W1e = (const float*)d_in[13];
    const float* W2e = (const float*)d_in[14];
    const float* g1n = (const float*)d_in[15];
    const float* b1n = (const float*)d_in[16];
    const float* g1e = (const float*)d_in[17];
    const float* b1e = (const float*)d_in[18];
    const float* g2n = (const float*)d_in[19];
    const float* b2n = (const float*)d_in[20];
    const float* g2e = (const float*)d_in[21];
    const float* b2e = (const float*)d_in[22];

    const int N = in_sizes[0] / 128;
    const int E = in_sizes[1] / 128;
    float* out = (float*)d_out;

    __half *Q, *Kb, *Vb, *PE;
    float *wV, *z;
    char* wim;
    cudaGetSymbolAddress((void**)&Q, g_Q);
    cudaGetSymbolAddress((void**)&Kb, g_Kb);
    cudaGetSymbolAddress((void**)&Vb, g_Vb);
    cudaGetSymbolAddress((void**)&PE, g_PE);
    cudaGetSymbolAddress((void**)&wV, g_wV);
    cudaGetSymbolAddress((void**)&z, g_z);
    cudaGetSymbolAddress((void**)&wim, g_wimg);

    auto IM = [&](int i) { return wim + (size_t)i * 81920; };

    const int SMG = 2 * TILEB;             // 69632
    const int SMO = 4 * TILEB + 65536;     // 204800
    cudaFuncSetAttribute((const void*)proj_gemm_all, cudaFuncAttributeMaxDynamicSharedMemorySize, SMG);
    cudaFuncSetAttribute((const void*)out_ffn_all, cudaFuncAttributeMaxDynamicSharedMemorySize, SMO);

    const int TtN = (N + 127) / 128;
    const int TtE = (E + 127) / 128;

    // 0) weight images + accumulator zeroing
    prep_all<<<dim3(128, 10), 256>>>(Wq, Wk, Wv, We, Wo_n, Wo_e, W1n, W1e, W2n, W2e, wim);
    zero2_kernel<<<2048, 256>>>(wV, (size_t)N * 128, z, (size_t)N * 8);

    // 1) merged projections: LN1+QKV (node) and LN1e+PE (edge) in one launch
    proj_gemm_all<<<3 * TtN + TtE, 256, SMG>>>(TtN, node, edge, g1n, b1n, g1e, b1e,
                                               IM(0), Q, Kb, Vb, PE, N, E);

    // 2) per-edge attention + aggregation (warp-per-edge, coalesced)
    edge_kernel<<<(E + 7) / 8, 256>>>(Q, Kb, Vb, PE, eidx, wV, z, E);

    // 3) merged fused output chains (node tiles first, then edge tiles), 512 threads
    out_ffn_all<<<TtN + TtE, 512, SMO>>>(TtN, N, E, wV, z, PE,
                                         IM(4), IM(5), bo_n, bo_e, node, edge,
                                         IM(6), IM(7), IM(8), IM(9),
                                         g2n, b2n, g2e, b2e, out);
}

// round 12
// speedup vs baseline: 1.2408x; 1.0320x over previous
#include <cuda_runtime.h>
#include <cuda_fp16.h>
#include <math.h>
#include <stdint.h>

// ================= scratch (device globals) =================
#define NMAX 50000
#define EMAX 400000

__device__ __half g_Q [(size_t)NMAX * 128];
__device__ __half g_Kb[(size_t)NMAX * 128];
__device__ __half g_Vb[(size_t)NMAX * 128];
__device__ __half g_PE[(size_t)EMAX * 128];   // PE -> overwritten with e_attn
__device__ float g_wV [(size_t)NMAX * 128];
__device__ float g_z  [(size_t)NMAX * 8];
// weight images: [n][k] fp16, k padded by 8; 10 slots x 80KB
__device__ char g_wimg[10][81920];

#define SMSB 272  // smem k-stride in bytes (136 fp16)
#define TILEB (128 * SMSB)

// ================= PTX helpers =================
__device__ __forceinline__ uint32_t smem_u32(const void* p) {
    uint32_t a;
    asm("{ .reg .u64 t; cvta.to.shared.u64 t, %1; cvt.u32.u64 %0, t; }" : "=r"(a) : "l"(p));
    return a;
}
__device__ __forceinline__ void cpa16(uint32_t d, const void* s) {
    asm volatile("cp.async.cg.shared.global [%0], [%1], 16;" :: "r"(d), "l"(s));
}
#define CPA_COMMIT() asm volatile("cp.async.commit_group;" ::: "memory")
#define CPA_WAIT(n)  asm volatile("cp.async.wait_group %0;" :: "n"(n) : "memory")

__device__ __forceinline__ void red_add_v4(float* p, float a, float b, float c, float d) {
    asm volatile("red.global.add.v4.f32 [%0], {%1, %2, %3, %4};"
                 :: "l"(p), "f"(a), "f"(b), "f"(c), "f"(d) : "memory");
}
__device__ __forceinline__ void red_add_f(float* p, float a) {
    asm volatile("red.global.add.f32 [%0], %1;" :: "l"(p), "f"(a) : "memory");
}

__device__ __forceinline__ void mma_f16(float* c, const uint32_t* a, const uint32_t* b) {
    asm volatile(
        "mma.sync.aligned.m16n8k16.row.col.f32.f16.f16.f32 "
        "{%0,%1,%2,%3}, {%4,%5,%6,%7}, {%8,%9}, {%0,%1,%2,%3};"
        : "+f"(c[0]), "+f"(c[1]), "+f"(c[2]), "+f"(c[3])
        : "r"(a[0]), "r"(a[1]), "r"(a[2]), "r"(a[3]), "r"(b[0]), "r"(b[1]));
}

// 128x128x128 fp16 tile compute; 16 warps in 4x4 (warp tile 32x32); acc accumulates.
__device__ __forceinline__ void compute_tile16(float (&acc)[2][4][4],
                                               const char* a_sm, const char* b_sm,
                                               int wm, int wn, int q, int t2) {
#pragma unroll
    for (int ks = 0; ks < 8; ks++) {
        uint32_t av[2][4], bv[4][2];
#pragma unroll
        for (int mt = 0; mt < 2; mt++) {
            int off = (wm * 32 + mt * 16 + q) * SMSB + (ks * 16 + t2) * 2;
            av[mt][0] = *(const uint32_t*)(a_sm + off);
            av[mt][1] = *(const uint32_t*)(a_sm + off + 8 * SMSB);
            av[mt][2] = *(const uint32_t*)(a_sm + off + 16);
            av[mt][3] = *(const uint32_t*)(a_sm + off + 8 * SMSB + 16);
        }
#pragma unroll
        for (int nt = 0; nt < 4; nt++) {
            int off = (wn * 32 + nt * 8 + q) * SMSB + (ks * 16 + t2) * 2;
            bv[nt][0] = *(const uint32_t*)(b_sm + off);
            bv[nt][1] = *(const uint32_t*)(b_sm + off + 16);
        }
#pragma unroll
        for (int mt = 0; mt < 2; mt++)
#pragma unroll
            for (int nt = 0; nt < 4; nt++) mma_f16(acc[mt][nt], av[mt], bv[nt]);
    }
}

// A-load (rows of 128 fp32 -> fp16). ALOAD: 1 LN(P1=g,P2=b), 2 div-by-z(P1=z)
// NT = thread count (256 or 512)
template <int ALOAD, int NT>
__device__ __forceinline__ void load_A(const float* __restrict__ A,
                                       const float* __restrict__ P1,
                                       const float* __restrict__ P2,
                                       int M, int m0, char* a_sm, int tid) {
    const int lane = tid & 31;
    float4 gg, bb;
    if (ALOAD == 1) {
        gg = *(const float4*)(P1 + lane * 4);
        bb = *(const float4*)(P2 + lane * 4);
    }
#pragma unroll 4
    for (int i = tid; i < 4096; i += NT) {
        int row = i >> 5;
        float4 v = make_float4(0.f, 0.f, 0.f, 0.f);
        bool valid = (m0 + row < M);
        if (valid) v = *(const float4*)(A + (size_t)(m0 + row) * 128 + lane * 4);
        if (ALOAD == 1) {
            float s = v.x + v.y + v.z + v.w;
#pragma unroll
            for (int o = 16; o; o >>= 1) s += __shfl_xor_sync(0xffffffffu, s, o);
            float mu = s * 0.0078125f;
            float d0 = v.x - mu, d1 = v.y - mu, d2 = v.z - mu, d3 = v.w - mu;
            float qq = d0 * d0 + d1 * d1 + d2 * d2 + d3 * d3;
#pragma unroll
            for (int o = 16; o; o >>= 1) qq += __shfl_xor_sync(0xffffffffu, qq, o);
            float inv = rsqrtf(qq * 0.0078125f + 1e-5f);
            v.x = d0 * inv * gg.x + bb.x;
            v.y = d1 * inv * gg.y + bb.y;
            v.z = d2 * inv * gg.z + bb.z;
            v.w = d3 * inv * gg.w + bb.w;
        } else if (ALOAD == 2) {
            float zz = valid ? P1[(size_t)(m0 + row) * 8 + (lane >> 2)] : 1.0f;
            float inv = 1.0f / (zz + 1e-6f);
            v.x *= inv; v.y *= inv; v.z *= inv; v.w *= inv;
        }
        __half2 p0 = __floats2half2_rn(v.x, v.y);
        __half2 p1 = __floats2half2_rn(v.z, v.w);
        uint2 P;
        P.x = *(const uint32_t*)&p0;
        P.y = *(const uint32_t*)&p1;
        *(uint2*)(a_sm + row * SMSB + lane * 8) = P;
    }
}

// ======= merged projection GEMM: QKV (node, slots 0-2) + PE (edge, slot 3) =======
// 512 threads, 16 warps (4x4), occ 2 -> 8 warps/SMSP.
__global__ __launch_bounds__(512, 2)
void proj_gemm_all(int TtN, const float* __restrict__ nodef,
                   const float* __restrict__ edgef, const float* __restrict__ g1n,
                   const float* __restrict__ b1n, const float* __restrict__ g1e,
                   const float* __restrict__ b1e, const char* __restrict__ WimgBase,
                   __half* __restrict__ Q, __half* __restrict__ Kb,
                   __half* __restrict__ Vb, __half* __restrict__ PE,
                   int Nn, int Ee) {
    extern __shared__ char smem[];
    char* a_sm = smem;
    char* b_sm = a_sm + TILEB;
    const uint32_t sb_b = smem_u32(smem) + TILEB;

    const int tid = threadIdx.x, wid = tid >> 5, lane = tid & 31;
    const int wm = wid >> 2, wn = wid & 3;
    const int q = lane >> 2, t2 = (lane & 3) * 2;

    const int bid = blockIdx.x;
    const bool is_edge = (bid >= 3 * TtN);
    const int slot = is_edge ? 3 : (bid / TtN);
    const int m0 = (is_edge ? (bid - 3 * TtN) : (bid % TtN)) * 128;
    const int M = is_edge ? Ee : Nn;
    const float* A = is_edge ? edgef : nodef;
    const float* g = is_edge ? g1e : g1n;
    const float* b = is_edge ? b1e : b1n;
    __half* C = (slot == 0) ? Q : (slot == 1) ? Kb : (slot == 2) ? Vb : PE;
    const char* Bg = WimgBase + (size_t)slot * 81920;

    for (int i = tid * 16; i < TILEB; i += 8192) cpa16(sb_b + i, Bg + i);
    CPA_COMMIT();

    float acc[2][4][4];
#pragma unroll
    for (int mt = 0; mt < 2; mt++)
#pragma unroll
        for (int nt = 0; nt < 4; nt++)
#pragma unroll
            for (int j = 0; j < 4; j++) acc[mt][nt][j] = 0.0f;

    load_A<1, 512>(A, g, b, M, m0, a_sm, tid);
    CPA_WAIT(0);
    __syncthreads();
    compute_tile16(acc, a_sm, b_sm, wm, wn, q, t2);

#pragma unroll
    for (int mt = 0; mt < 2; mt++) {
#pragma unroll
        for (int half = 0; half < 2; half++) {
            int row = m0 + wm * 32 + mt * 16 + q + half * 8;
            if (row >= M) continue;
#pragma unroll
            for (int nt = 0; nt < 4; nt++) {
                int col = wn * 32 + nt * 8 + t2;
                __half2 hp = __floats2half2_rn(acc[mt][nt][half * 2 + 0],
                                               acc[mt][nt][half * 2 + 1]);
                *(uint32_t*)((char*)C + ((size_t)row * 128 + col) * 2) =
                    *(const uint32_t*)&hp;
            }
        }
    }
}

// ================= per-edge attention (one warp per edge, fp16 tensors) =================
__global__ void edge_kernel(const __half* __restrict__ Q, const __half* __restrict__ K,
                            const __half* __restrict__ V, __half* __restrict__ PE,
                            const int* __restrict__ eidx, float* __restrict__ wV,
                            float* __restrict__ z, int E) {
    int e = blockIdx.x * 8 + (threadIdx.x >> 5);
    if (e >= E) return;
    int lane = threadIdx.x & 31;
    int src = eidx[e];
    int dst = eidx[E + e];
    int i = lane * 4;
    uint2 ku = *(const uint2*)(K + (size_t)src * 128 + i);
    uint2 qu = *(const uint2*)(Q + (size_t)dst * 128 + i);
    uint2 pu = *(const uint2*)(PE + (size_t)e * 128 + i);
    float2 k0 = __half22float2(*(__half2*)&ku.x), k1 = __half22float2(*(__half2*)&ku.y);
    float2 q0 = __half22float2(*(__half2*)&qu.x), q1 = __half22float2(*(__half2*)&qu.y);
    float2 p0 = __half22float2(*(__half2*)&pu.x), p1 = __half22float2(*(__half2*)&pu.y);
    const float sc = 0.25f;
    float s0 = fminf(fmaxf(k0.x * q0.x * sc, -5.0f), 5.0f) * p0.x;
    float s1 = fminf(fmaxf(k0.y * q0.y * sc, -5.0f), 5.0f) * p0.y;
    float s2 = fminf(fmaxf(k1.x * q1.x * sc, -5.0f), 5.0f) * p1.x;
    float s3 = fminf(fmaxf(k1.y * q1.y * sc, -5.0f), 5.0f) * p1.y;
    __half2 e0 = __floats2half2_rn(s0, s1), e1 = __floats2half2_rn(s2, s3);
    uint2 eo;
    eo.x = *(const uint32_t*)&e0;
    eo.y = *(const uint32_t*)&e1;
    *(uint2*)(PE + (size_t)e * 128 + i) = eo;

    float hs = s0 + s1 + s2 + s3;
    hs += __shfl_xor_sync(0xffffffffu, hs, 1);
    hs += __shfl_xor_sync(0xffffffffu, hs, 2);
    float w = expf(fminf(fmaxf(hs, -5.0f), 5.0f));

    uint2 vu = *(const uint2*)(V + (size_t)src * 128 + i);
    float2 v0 = __half22float2(*(__half2*)&vu.x), v1 = __half22float2(*(__half2*)&vu.y);
    red_add_v4(wV + (size_t)dst * 128 + i, v0.x * w, v0.y * w, v1.x * w, v1.y * w);
    if ((lane & 3) == 0)
        red_add_f(z + (size_t)dst * 8 + (lane >> 2), w);
}

// ====== merged fused output chain (node + edge, one grid), 512 threads ======
// out = x2 + FFN(LN2(x2)),  x2 = R + bias + op(A)@Wo
__global__ __launch_bounds__(512, 1)
void out_ffn_all(int TtN, int Nn, int Ee, const float* __restrict__ wV,
                 const float* __restrict__ z, const __half* __restrict__ eattn,
                 const char* __restrict__ WoN, const char* __restrict__ WoE,
                 const float* __restrict__ boN, const float* __restrict__ boE,
                 const float* __restrict__ nodeR, const float* __restrict__ edgeR,
                 const char* __restrict__ W1N, const char* __restrict__ W1E,
                 const char* __restrict__ W2N, const char* __restrict__ W2E,
                 const float* __restrict__ gN, const float* __restrict__ bN,
                 const float* __restrict__ gE, const float* __restrict__ bE,
                 float* __restrict__ outBase) {
    extern __shared__ char smem[];
    char* a_sm = smem;
    char* w0 = a_sm + TILEB;
    char* w1 = w0 + TILEB;
    char* t_sm = w1 + TILEB;
    char* x_sm = t_sm + TILEB;
    const uint32_t sb = smem_u32(smem);
    const uint32_t s_w0 = sb + TILEB, s_w1 = s_w0 + TILEB;
    const uint32_t s_x = sb + 4 * TILEB;

    const int tid = threadIdx.x, wid = tid >> 5, lane = tid & 31;
    const int wm = wid >> 2, wn = wid & 3;   // 4x4 warp grid, warp tile 32x32
    const int q = lane >> 2, t2 = (lane & 3) * 2;

    const bool is_edge = ((int)blockIdx.x >= TtN);
    const int m0 = (is_edge ? (blockIdx.x - TtN) : blockIdx.x) * 128;
    const int M = is_edge ? Ee : Nn;
    const char* Wo = is_edge ? WoE : WoN;
    const float* bias = is_edge ? boE : boN;
    const float* R = is_edge ? edgeR : nodeR;
    const char* W1 = is_edge ? W1E : W1N;
    const char* W2 = is_edge ? W2E : W2N;
    const float* g = is_edge ? gE : gN;
    const float* b = is_edge ? bE : bN;
    float* out = is_edge ? (outBase + (size_t)Nn * 128) : outBase;

    // G0: Wo -> w0, R -> x_sm, (edge: fp16 A -> a_sm)
    for (int i = tid * 16; i < TILEB; i += 8192) cpa16(s_w0 + i, Wo + i);
    for (int i = tid; i < 128 * 32; i += 512) {
        int row = i >> 5, j = i & 31;
        if (m0 + row < M)
            cpa16(s_x + row * 512 + j * 16,
                  (const char*)R + ((size_t)(m0 + row) * 512 + j * 16));
    }
    if (is_edge) {
        for (int i = tid; i < 128 * 16; i += 512) {
            int row = i >> 4, j = i & 15;
            if (m0 + row < M)
                cpa16(sb + row * SMSB + j * 16,
                      (const char*)eattn + (size_t)(m0 + row) * 256 + j * 16);
        }
    }
    CPA_COMMIT();
    // G1: W1 half0 -> w1
    for (int i = tid * 16; i < TILEB; i += 8192) cpa16(s_w1 + i, W1 + i);
    CPA_COMMIT();

    if (!is_edge) load_A<2, 512>(wV, z, nullptr, M, m0, a_sm, tid);

    float acc1[2][4][4];
#pragma unroll
    for (int mt = 0; mt < 2; mt++)
#pragma unroll
        for (int nt = 0; nt < 4; nt++)
#pragma unroll
            for (int j = 0; j < 4; j++) acc1[mt][nt][j] = 0.0f;

    CPA_WAIT(1);  // G0 done
    __syncthreads();
    compute_tile16(acc1, a_sm, w0, wm, wn, q, t2);  // op(A) @ Wo
    __syncthreads();
    // G2: W2 chunk0 -> w0
    for (int i = tid; i < 128 * 16; i += 512) {
        int n = i >> 4, j = i & 15;
        cpa16(s_w0 + n * SMSB + j * 16, W2 + (size_t)n * 528 + j * 16);
    }
    CPA_COMMIT();

    // x2 tile into x_sm: x += acc + bias
#pragma unroll
    for (int mt = 0; mt < 2; mt++)
#pragma unroll
        for (int half = 0; half < 2; half++) {
            int lrow = wm * 32 + mt * 16 + q + half * 8;
#pragma unroll
            for (int nt = 0; nt < 4; nt++) {
                int col = wn * 32 + nt * 8 + t2;
                float2 bbv = *(const float2*)(bias + col);
                float2 xx = *(const float2*)(x_sm + lrow * 512 + col * 4);
                xx.x += acc1[mt][nt][half * 2 + 0] + bbv.x;
                xx.y += acc1[mt][nt][half * 2 + 1] + bbv.y;
                *(float2*)(x_sm + lrow * 512 + col * 4) = xx;
            }
        }
    __syncthreads();

    // LN2 over x_sm rows -> a_sm (fp16)
    {
        float4 gg = *(const float4*)(g + lane * 4);
        float4 bb = *(const float4*)(b + lane * 4);
#pragma unroll 4
        for (int i = tid; i < 4096; i += 512) {
            int row = i >> 5;
            float4 v = *(const float4*)(x_sm + row * 512 + lane * 16);
            float s = v.x + v.y + v.z + v.w;
#pragma unroll
            for (int o = 16; o; o >>= 1) s += __shfl_xor_sync(0xffffffffu, s, o);
            float mu = s * 0.0078125f;
            float d0 = v.x - mu, d1 = v.y - mu, d2 = v.z - mu, d3 = v.w - mu;
            float qq = d0 * d0 + d1 * d1 + d2 * d2 + d3 * d3;
#pragma unroll
            for (int o = 16; o; o >>= 1) qq += __shfl_xor_sync(0xffffffffu, qq, o);
            float inv = rsqrtf(qq * 0.0078125f + 1e-5f);
            __half2 p0 = __floats2half2_rn(d0 * inv * gg.x + bb.x, d1 * inv * gg.y + bb.y);
            __half2 p1 = __floats2half2_rn(d2 * inv * gg.z + bb.z, d3 * inv * gg.w + bb.w);
            uint2 P;
            P.x = *(const uint32_t*)&p0;
            P.y = *(const uint32_t*)&p1;
            *(uint2*)(a_sm + row * SMSB + lane * 8) = P;
        }
    }
    __syncthreads();

    float acc2[2][4][4];
#pragma unroll
    for (int mt = 0; mt < 2; mt++)
#pragma unroll
        for (int nt = 0; nt < 4; nt++)
#pragma unroll
            for (int j = 0; j < 4; j++) acc2[mt][nt][j] = 0.0f;

#pragma unroll
    for (int h = 0; h < 2; h++) {
        CPA_WAIT(1);  // h=0: G1 (w1=W1h0); h=1: G3 (w1=W1h1)
        __syncthreads();
#pragma unroll
        for (int mt = 0; mt < 2; mt++)
#pragma unroll
            for (int nt = 0; nt < 4; nt++)
#pragma unroll
                for (int j = 0; j < 4; j++) acc1[mt][nt][j] = 0.0f;
        compute_tile16(acc1, a_sm, w1, wm, wn, q, t2);
        __syncthreads();
        if (h == 0) {
            for (int i = tid * 16; i < TILEB; i += 8192) cpa16(s_w1 + i, W1 + TILEB + i);
            CPA_COMMIT();
        }
        // silu -> t_sm (fp16)
#pragma unroll
        for (int mt = 0; mt < 2; mt++)
#pragma unroll
            for (int nt = 0; nt < 4; nt++) {
                int row0 = wm * 32 + mt * 16 + q;
                int col = wn * 32 + nt * 8 + t2;
#pragma unroll
                for (int half = 0; half < 2; half++) {
                    float s0 = acc1[mt][nt][half * 2 + 0];
                    float s1 = acc1[mt][nt][half * 2 + 1];
                    s0 = s0 / (1.0f + expf(-s0));
                    s1 = s1 / (1.0f + expf(-s1));
                    __half2 p = __floats2half2_rn(s0, s1);
                    *(uint32_t*)(t_sm + (row0 + half * 8) * SMSB + col * 2) =
                        *(const uint32_t*)&p;
                }
            }
        if (h == 0) CPA_WAIT(1); else CPA_WAIT(0);  // W2 chunk in w0
        __syncthreads();
        compute_tile16(acc2, t_sm, w0, wm, wn, q, t2);
        __syncthreads();
        if (h == 0) {
            for (int i = tid; i < 128 * 16; i += 512) {
                int n = i >> 4, j = i & 15;
                cpa16(s_w0 + n * SMSB + j * 16, W2 + (size_t)n * 528 + 256 + j * 16);
            }
            CPA_COMMIT();
        }
    }

    // epilogue: out = x_sm (x2) + acc2
#pragma unroll
    for (int mt = 0; mt < 2; mt++) {
#pragma unroll
        for (int half = 0; half < 2; half++) {
            int lrow = wm * 32 + mt * 16 + q + half * 8;
            int row = m0 + lrow;
            if (row >= M) continue;
#pragma unroll
            for (int nt = 0; nt < 4; nt++) {
                int col = wn * 32 + nt * 8 + t2;
                float2 rr = *(const float2*)(x_sm + lrow * 512 + col * 4);
                float o0 = acc2[mt][nt][half * 2 + 0] + rr.x;
                float o1 = acc2[mt][nt][half * 2 + 1] + rr.y;
                *(float2*)(out + (size_t)row * 128 + col) = make_float2(o0, o1);
            }
        }
    }
}

// ====== weight prep: all 10 weights, fp16, one launch ======
__global__ void prep_all(const float* w0, const float* w1, const float* w2,
                         const float* w3, const float* w4, const float* w5,
                         const float* w6, const float* w7, const float* w8,
                         const float* w9, char* __restrict__ ib) {
    int y = blockIdx.y;
    const float* W;
    int K = 128, N = 128;
    switch (y) {
        case 0: W = w0; break;
        case 1: W = w1; break;
        case 2: W = w2; break;
        case 3: W = w3; break;
        case 4: W = w4; break;
        case 5: W = w5; break;
        case 6: W = w6; N = 256; break;
        case 7: W = w7; N = 256; break;
        case 8: W = w8; K = 256; break;
        default: W = w9; K = 256; break;
    }
    int idx = blockIdx.x * 256 + threadIdx.x;
    if (idx >= K * N) return;
    int k = idx / N, n = idx % N;
    size_t off = (size_t)y * 81920 + ((size_t)n * (K + 8) + k) * 2;
    *(unsigned short*)(ib + off) = __half_as_ushort(__float2half_rn(W[idx]));
}

__global__ void zero2_kernel(float* __restrict__ a, size_t na,
                             float* __restrict__ bz, size_t nb) {
    size_t i = (size_t)blockIdx.x * blockDim.x + threadIdx.x;
    size_t st = (size_t)gridDim.x * blockDim.x;
    for (size_t k = i; k < na; k += st) a[k] = 0.0f;
    for (size_t k = i; k < nb; k += st) bz[k] = 0.0f;
}

// ================= launch =================
extern "C" void kernel_launch(void* const* d_in, const int* in_sizes, int n_in,
                              void* d_out, int out_size) {
    const float* node = (const float*)d_in[0];
    const float* edge = (const float*)d_in[1];
    const int*   eidx = (const int*)d_in[2];
    const float* Wq = (const float*)d_in[3];
    const float* Wk = (const float*)d_in[4];
    const float* Wv = (const float*)d_in[5];
    const float* We = (const float*)d_in[6];
    const float* Wo_n = (const float*)d_in[7];
    const float* bo_n = (const float*)d_in[8];
    const float* Wo_e = (const float*)d_in[9];
    const float* bo_e = (const float*)d_in[10];
    const float* W1n = (const float*)d_in[11];
    const float* W2n = (const float*)d_in[12];
    const float* W1e = (const float*)d_in[13];
    const float* W2e = (const float*)d_in[14];
    const float* g1n = (const float*)d_in[15];
    const float* b1n = (const float*)d_in[16];
    const float* g1e = (const float*)d_in[17];
    const float* b1e = (const float*)d_in[18];
    const float* g2n = (const float*)d_in[19];
    const float* b2n = (const float*)d_in[20];
    const float* g2e = (const float*)d_in[21];
    const float* b2e = (const float*)d_in[22];

    const int N = in_sizes[0] / 128;
    const int E = in_sizes[1] / 128;
    float* out = (float*)d_out;

    __half *Q, *Kb, *Vb, *PE;
    float *wV, *z;
    char* wim;
    cudaGetSymbolAddress((void**)&Q, g_Q);
    cudaGetSymbolAddress((void**)&Kb, g_Kb);
    cudaGetSymbolAddress((void**)&Vb, g_Vb);
    cudaGetSymbolAddress((void**)&PE, g_PE);
    cudaGetSymbolAddress((void**)&wV, g_wV);
    cudaGetSymbolAddress((void**)&z, g_z);
    cudaGetSymbolAddress((void**)&wim, g_wimg);

    auto IM = [&](int i) { return wim + (size_t)i * 81920; };

    const int SMG = 2 * TILEB;             // 69632
    const int SMO = 4 * TILEB + 65536;     // 204800
    cudaFuncSetAttribute((const void*)proj_gemm_all, cudaFuncAttributeMaxDynamicSharedMemorySize, SMG);
    cudaFuncSetAttribute((const void*)out_ffn_all, cudaFuncAttributeMaxDynamicSharedMemorySize, SMO);

    const int TtN = (N + 127) / 128;
    const int TtE = (E + 127) / 128;

    // 0) weight images + accumulator zeroing
    prep_all<<<dim3(128, 10), 256>>>(Wq, Wk, Wv, We, Wo_n, Wo_e, W1n, W1e, W2n, W2e, wim);
    zero2_kernel<<<2048, 256>>>(wV, (size_t)N * 128, z, (size_t)N * 8);

    // 1) merged projections: LN1+QKV (node) and LN1e+PE (edge), 512 threads occ2
    proj_gemm_all<<<3 * TtN + TtE, 512, SMG>>>(TtN, node, edge, g1n, b1n, g1e, b1e,
                                               IM(0), Q, Kb, Vb, PE, N, E);

    // 2) per-edge attention + aggregation (warp-per-edge, coalesced)
    edge_kernel<<<(E + 7) / 8, 256>>>(Q, Kb, Vb, PE, eidx, wV, z, E);

    // 3) merged fused output chains (node tiles first, then edge tiles), 512 threads
    out_ffn_all<<<TtN + TtE, 512, SMO>>>(TtN, N, E, wV, z, PE,
                                         IM(4), IM(5), bo_n, bo_e, node, edge,
                                         IM(6), IM(7), IM(8), IM(9),
                                         g2n, b2n, g2e, b2e, out);
}

// round 13
// speedup vs baseline: 1.2602x; 1.0157x over previous
#include <cuda_runtime.h>
#include <cuda_fp16.h>
#include <math.h>
#include <stdint.h>

// ================= scratch (device globals) =================
#define NMAX 50000
#define EMAX 400000

__device__ __half g_Q [(size_t)NMAX * 128];
__device__ __half g_Kb[(size_t)NMAX * 128];
__device__ __half g_Vb[(size_t)NMAX * 128];
__device__ __half g_PE[(size_t)EMAX * 128];   // PE -> overwritten with e_attn
__device__ float g_wV [(size_t)NMAX * 128];
__device__ float g_z  [(size_t)NMAX * 8];
// weight images: [n][k] fp16, k padded by 8; 10 slots x 80KB
__device__ char g_wimg[10][81920];

#define SMSB 272  // smem k-stride in bytes (136 fp16)
#define TILEB (128 * SMSB)

// ================= PTX helpers =================
__device__ __forceinline__ uint32_t smem_u32(const void* p) {
    uint32_t a;
    asm("{ .reg .u64 t; cvta.to.shared.u64 t, %1; cvt.u32.u64 %0, t; }" : "=r"(a) : "l"(p));
    return a;
}
__device__ __forceinline__ void cpa16(uint32_t d, const void* s) {
    asm volatile("cp.async.cg.shared.global [%0], [%1], 16;" :: "r"(d), "l"(s));
}
#define CPA_COMMIT() asm volatile("cp.async.commit_group;" ::: "memory")
#define CPA_WAIT(n)  asm volatile("cp.async.wait_group %0;" :: "n"(n) : "memory")

__device__ __forceinline__ void red_add_v4(float* p, float a, float b, float c, float d) {
    asm volatile("red.global.add.v4.f32 [%0], {%1, %2, %3, %4};"
                 :: "l"(p), "f"(a), "f"(b), "f"(c), "f"(d) : "memory");
}
__device__ __forceinline__ void red_add_f(float* p, float a) {
    asm volatile("red.global.add.f32 [%0], %1;" :: "l"(p), "f"(a) : "memory");
}

__device__ __forceinline__ void mma_f16b(float* c, const uint32_t* a,
                                         uint32_t b0, uint32_t b1) {
    asm volatile(
        "mma.sync.aligned.m16n8k16.row.col.f32.f16.f16.f32 "
        "{%0,%1,%2,%3}, {%4,%5,%6,%7}, {%8,%9}, {%0,%1,%2,%3};"
        : "+f"(c[0]), "+f"(c[1]), "+f"(c[2]), "+f"(c[3])
        : "r"(a[0]), "r"(a[1]), "r"(a[2]), "r"(a[3]), "r"(b0), "r"(b1));
}
__device__ __forceinline__ void ldsm_x4(uint32_t* r, uint32_t addr) {
    asm volatile("ldmatrix.sync.aligned.m8n8.x4.shared.b16 {%0,%1,%2,%3}, [%4];"
                 : "=r"(r[0]), "=r"(r[1]), "=r"(r[2]), "=r"(r[3]) : "r"(addr));
}

// 128x128x128 fp16 tile compute; 16 warps in 4x4 (warp tile 32x32); acc accumulates.
// ldmatrix-fed: 4 LDSM.x4 + 8 HMMA per k-step per warp.
__device__ __forceinline__ void compute_tile16(float (&acc)[2][4][4],
                                               uint32_t a_u32, uint32_t b_u32,
                                               int wm, int wn, int lane) {
    const int r = lane & 7, frag = lane >> 3;
    const int fr8 = (frag & 1) * 8, fc16 = (frag >> 1) * 16;
    // A: x4 covers m16k16 fragments a0..a3 for one mt block
    uint32_t aaddr0 = a_u32 + (wm * 32 + fr8 + r) * SMSB + fc16;
    uint32_t aaddr1 = aaddr0 + 16 * SMSB;
    // B: x4 covers {b[nt][0],b[nt][1],b[nt+1][0],b[nt+1][1]} (8 n-rows per nt)
    uint32_t baddr0 = b_u32 + (wn * 32 + (frag >> 1) * 8 + r) * SMSB + (frag & 1) * 16;
    uint32_t baddr1 = baddr0 + 16 * SMSB;
#pragma unroll
    for (int ks = 0; ks < 8; ks++) {
        uint32_t av0[4], av1[4], bv0[4], bv1[4];
        ldsm_x4(av0, aaddr0 + ks * 32);
        ldsm_x4(av1, aaddr1 + ks * 32);
        ldsm_x4(bv0, baddr0 + ks * 32);
        ldsm_x4(bv1, baddr1 + ks * 32);
        mma_f16b(acc[0][0], av0, bv0[0], bv0[1]);
        mma_f16b(acc[0][1], av0, bv0[2], bv0[3]);
        mma_f16b(acc[0][2], av0, bv1[0], bv1[1]);
        mma_f16b(acc[0][3], av0, bv1[2], bv1[3]);
        mma_f16b(acc[1][0], av1, bv0[0], bv0[1]);
        mma_f16b(acc[1][1], av1, bv0[2], bv0[3]);
        mma_f16b(acc[1][2], av1, bv1[0], bv1[1]);
        mma_f16b(acc[1][3], av1, bv1[2], bv1[3]);
    }
}

// A-load (rows of 128 fp32 -> fp16). ALOAD: 1 LN(P1=g,P2=b), 2 div-by-z(P1=z)
template <int ALOAD, int NT>
__device__ __forceinline__ void load_A(const float* __restrict__ A,
                                       const float* __restrict__ P1,
                                       const float* __restrict__ P2,
                                       int M, int m0, char* a_sm, int tid) {
    const int lane = tid & 31;
    float4 gg, bb;
    if (ALOAD == 1) {
        gg = *(const float4*)(P1 + lane * 4);
        bb = *(const float4*)(P2 + lane * 4);
    }
#pragma unroll 4
    for (int i = tid; i < 4096; i += NT) {
        int row = i >> 5;
        float4 v = make_float4(0.f, 0.f, 0.f, 0.f);
        bool valid = (m0 + row < M);
        if (valid) v = *(const float4*)(A + (size_t)(m0 + row) * 128 + lane * 4);
        if (ALOAD == 1) {
            float s = v.x + v.y + v.z + v.w;
#pragma unroll
            for (int o = 16; o; o >>= 1) s += __shfl_xor_sync(0xffffffffu, s, o);
            float mu = s * 0.0078125f;
            float d0 = v.x - mu, d1 = v.y - mu, d2 = v.z - mu, d3 = v.w - mu;
            float qq = d0 * d0 + d1 * d1 + d2 * d2 + d3 * d3;
#pragma unroll
            for (int o = 16; o; o >>= 1) qq += __shfl_xor_sync(0xffffffffu, qq, o);
            float inv = rsqrtf(qq * 0.0078125f + 1e-5f);
            v.x = d0 * inv * gg.x + bb.x;
            v.y = d1 * inv * gg.y + bb.y;
            v.z = d2 * inv * gg.z + bb.z;
            v.w = d3 * inv * gg.w + bb.w;
        } else if (ALOAD == 2) {
            float zz = valid ? P1[(size_t)(m0 + row) * 8 + (lane >> 2)] : 1.0f;
            float inv = 1.0f / (zz + 1e-6f);
            v.x *= inv; v.y *= inv; v.z *= inv; v.w *= inv;
        }
        __half2 p0 = __floats2half2_rn(v.x, v.y);
        __half2 p1 = __floats2half2_rn(v.z, v.w);
        uint2 P;
        P.x = *(const uint32_t*)&p0;
        P.y = *(const uint32_t*)&p1;
        *(uint2*)(a_sm + row * SMSB + lane * 8) = P;
    }
}

// ======= merged projection GEMM: QKV (node, slots 0-2) + PE (edge, slot 3) =======
__global__ __launch_bounds__(512, 2)
void proj_gemm_all(int TtN, const float* __restrict__ nodef,
                   const float* __restrict__ edgef, const float* __restrict__ g1n,
                   const float* __restrict__ b1n, const float* __restrict__ g1e,
                   const float* __restrict__ b1e, const char* __restrict__ WimgBase,
                   __half* __restrict__ Q, __half* __restrict__ Kb,
                   __half* __restrict__ Vb, __half* __restrict__ PE,
                   int Nn, int Ee) {
    extern __shared__ char smem[];
    char* a_sm = smem;
    const uint32_t sb = smem_u32(smem);
    const uint32_t sb_b = sb + TILEB;

    const int tid = threadIdx.x, wid = tid >> 5, lane = tid & 31;
    const int wm = wid >> 2, wn = wid & 3;
    const int q = lane >> 2, t2 = (lane & 3) * 2;

    const int bid = blockIdx.x;
    const bool is_edge = (bid >= 3 * TtN);
    const int slot = is_edge ? 3 : (bid / TtN);
    const int m0 = (is_edge ? (bid - 3 * TtN) : (bid % TtN)) * 128;
    const int M = is_edge ? Ee : Nn;
    const float* A = is_edge ? edgef : nodef;
    const float* g = is_edge ? g1e : g1n;
    const float* b = is_edge ? b1e : b1n;
    __half* C = (slot == 0) ? Q : (slot == 1) ? Kb : (slot == 2) ? Vb : PE;
    const char* Bg = WimgBase + (size_t)slot * 81920;

    for (int i = tid * 16; i < TILEB; i += 8192) cpa16(sb_b + i, Bg + i);
    CPA_COMMIT();

    float acc[2][4][4];
#pragma unroll
    for (int mt = 0; mt < 2; mt++)
#pragma unroll
        for (int nt = 0; nt < 4; nt++)
#pragma unroll
            for (int j = 0; j < 4; j++) acc[mt][nt][j] = 0.0f;

    load_A<1, 512>(A, g, b, M, m0, a_sm, tid);
    CPA_WAIT(0);
    __syncthreads();
    compute_tile16(acc, sb, sb_b, wm, wn, lane);

#pragma unroll
    for (int mt = 0; mt < 2; mt++) {
#pragma unroll
        for (int half = 0; half < 2; half++) {
            int row = m0 + wm * 32 + mt * 16 + q + half * 8;
            if (row >= M) continue;
#pragma unroll
            for (int nt = 0; nt < 4; nt++) {
                int col = wn * 32 + nt * 8 + t2;
                __half2 hp = __floats2half2_rn(acc[mt][nt][half * 2 + 0],
                                               acc[mt][nt][half * 2 + 1]);
                *(uint32_t*)((char*)C + ((size_t)row * 128 + col) * 2) =
                    *(const uint32_t*)&hp;
            }
        }
    }
}

// ================= per-edge attention (one warp per edge, fp16 tensors) =================
__global__ void edge_kernel(const __half* __restrict__ Q, const __half* __restrict__ K,
                            const __half* __restrict__ V, __half* __restrict__ PE,
                            const int* __restrict__ eidx, float* __restrict__ wV,
                            float* __restrict__ z, int E) {
    int e = blockIdx.x * 8 + (threadIdx.x >> 5);
    if (e >= E) return;
    int lane = threadIdx.x & 31;
    int src = eidx[e];
    int dst = eidx[E + e];
    int i = lane * 4;
    uint2 ku = *(const uint2*)(K + (size_t)src * 128 + i);
    uint2 qu = *(const uint2*)(Q + (size_t)dst * 128 + i);
    uint2 pu = *(const uint2*)(PE + (size_t)e * 128 + i);
    float2 k0 = __half22float2(*(__half2*)&ku.x), k1 = __half22float2(*(__half2*)&ku.y);
    float2 q0 = __half22float2(*(__half2*)&qu.x), q1 = __half22float2(*(__half2*)&qu.y);
    float2 p0 = __half22float2(*(__half2*)&pu.x), p1 = __half22float2(*(__half2*)&pu.y);
    const float sc = 0.25f;
    float s0 = fminf(fmaxf(k0.x * q0.x * sc, -5.0f), 5.0f) * p0.x;
    float s1 = fminf(fmaxf(k0.y * q0.y * sc, -5.0f), 5.0f) * p0.y;
    float s2 = fminf(fmaxf(k1.x * q1.x * sc, -5.0f), 5.0f) * p1.x;
    float s3 = fminf(fmaxf(k1.y * q1.y * sc, -5.0f), 5.0f) * p1.y;
    __half2 e0 = __floats2half2_rn(s0, s1), e1 = __floats2half2_rn(s2, s3);
    uint2 eo;
    eo.x = *(const uint32_t*)&e0;
    eo.y = *(const uint32_t*)&e1;
    *(uint2*)(PE + (size_t)e * 128 + i) = eo;

    float hs = s0 + s1 + s2 + s3;
    hs += __shfl_xor_sync(0xffffffffu, hs, 1);
    hs += __shfl_xor_sync(0xffffffffu, hs, 2);
    float w = expf(fminf(fmaxf(hs, -5.0f), 5.0f));

    uint2 vu = *(const uint2*)(V + (size_t)src * 128 + i);
    float2 v0 = __half22float2(*(__half2*)&vu.x), v1 = __half22float2(*(__half2*)&vu.y);
    red_add_v4(wV + (size_t)dst * 128 + i, v0.x * w, v0.y * w, v1.x * w, v1.y * w);
    if ((lane & 3) == 0)
        red_add_f(z + (size_t)dst * 8 + (lane >> 2), w);
}

// ====== merged fused output chain (node + edge, one grid), 512 threads ======
__global__ __launch_bounds__(512, 1)
void out_ffn_all(int TtN, int Nn, int Ee, const float* __restrict__ wV,
                 const float* __restrict__ z, const __half* __restrict__ eattn,
                 const char* __restrict__ WoN, const char* __restrict__ WoE,
                 const float* __restrict__ boN, const float* __restrict__ boE,
                 const float* __restrict__ nodeR, const float* __restrict__ edgeR,
                 const char* __restrict__ W1N, const char* __restrict__ W1E,
                 const char* __restrict__ W2N, const char* __restrict__ W2E,
                 const float* __restrict__ gN, const float* __restrict__ bN,
                 const float* __restrict__ gE, const float* __restrict__ bE,
                 float* __restrict__ outBase) {
    extern __shared__ char smem[];
    char* a_sm = smem;
    char* x_sm = smem + 4 * TILEB;
    const uint32_t sb = smem_u32(smem);
    const uint32_t s_w0 = sb + TILEB, s_w1 = s_w0 + TILEB, s_t = s_w1 + TILEB;
    const uint32_t s_x = sb + 4 * TILEB;

    const int tid = threadIdx.x, wid = tid >> 5, lane = tid & 31;
    const int wm = wid >> 2, wn = wid & 3;   // 4x4 warp grid, warp tile 32x32
    const int q = lane >> 2, t2 = (lane & 3) * 2;

    const bool is_edge = ((int)blockIdx.x >= TtN);
    const int m0 = (is_edge ? (blockIdx.x - TtN) : blockIdx.x) * 128;
    const int M = is_edge ? Ee : Nn;
    const char* Wo = is_edge ? WoE : WoN;
    const float* bias = is_edge ? boE : boN;
    const float* R = is_edge ? edgeR : nodeR;
    const char* W1 = is_edge ? W1E : W1N;
    const char* W2 = is_edge ? W2E : W2N;
    const float* g = is_edge ? gE : gN;
    const float* b = is_edge ? bE : bN;
    float* out = is_edge ? (outBase + (size_t)Nn * 128) : outBase;

    // G0: Wo -> w0, R -> x_sm, (edge: fp16 A -> a_sm)
    for (int i = tid * 16; i < TILEB; i += 8192) cpa16(s_w0 + i, Wo + i);
    for (int i = tid; i < 128 * 32; i += 512) {
        int row = i >> 5, j = i & 31;
        if (m0 + row < M)
            cpa16(s_x + row * 512 + j * 16,
                  (const char*)R + ((size_t)(m0 + row) * 512 + j * 16));
    }
    if (is_edge) {
        for (int i = tid; i < 128 * 16; i += 512) {
            int row = i >> 4, j = i & 15;
            if (m0 + row < M)
                cpa16(sb + row * SMSB + j * 16,
                      (const char*)eattn + (size_t)(m0 + row) * 256 + j * 16);
        }
    }
    CPA_COMMIT();
    // G1: W1 half0 -> w1
    for (int i = tid * 16; i < TILEB; i += 8192) cpa16(s_w1 + i, W1 + i);
    CPA_COMMIT();

    if (!is_edge) load_A<2, 512>(wV, z, nullptr, M, m0, a_sm, tid);

    float acc1[2][4][4];
#pragma unroll
    for (int mt = 0; mt < 2; mt++)
#pragma unroll
        for (int nt = 0; nt < 4; nt++)
#pragma unroll
            for (int j = 0; j < 4; j++) acc1[mt][nt][j] = 0.0f;

    CPA_WAIT(1);  // G0 done
    __syncthreads();
    compute_tile16(acc1, sb, s_w0, wm, wn, lane);  // op(A) @ Wo
    __syncthreads();
    // G2: W2 chunk0 -> w0
    for (int i = tid; i < 128 * 16; i += 512) {
        int n = i >> 4, j = i & 15;
        cpa16(s_w0 + n * SMSB + j * 16, W2 + (size_t)n * 528 + j * 16);
    }
    CPA_COMMIT();

    // x2 tile into x_sm: x += acc + bias
#pragma unroll
    for (int mt = 0; mt < 2; mt++)
#pragma unroll
        for (int half = 0; half < 2; half++) {
            int lrow = wm * 32 + mt * 16 + q + half * 8;
#pragma unroll
            for (int nt = 0; nt < 4; nt++) {
                int col = wn * 32 + nt * 8 + t2;
                float2 bbv = *(const float2*)(bias + col);
                float2 xx = *(const float2*)(x_sm + lrow * 512 + col * 4);
                xx.x += acc1[mt][nt][half * 2 + 0] + bbv.x;
                xx.y += acc1[mt][nt][half * 2 + 1] + bbv.y;
                *(float2*)(x_sm + lrow * 512 + col * 4) = xx;
            }
        }
    __syncthreads();

    // LN2 over x_sm rows -> a_sm (fp16)
    {
        float4 gg = *(const float4*)(g + lane * 4);
        float4 bb = *(const float4*)(b + lane * 4);
#pragma unroll 4
        for (int i = tid; i < 4096; i += 512) {
            int row = i >> 5;
            float4 v = *(const float4*)(x_sm + row * 512 + lane * 16);
            float s = v.x + v.y + v.z + v.w;
#pragma unroll
            for (int o = 16; o; o >>= 1) s += __shfl_xor_sync(0xffffffffu, s, o);
            float mu = s * 0.0078125f;
            float d0 = v.x - mu, d1 = v.y - mu, d2 = v.z - mu, d3 = v.w - mu;
            float qq = d0 * d0 + d1 * d1 + d2 * d2 + d3 * d3;
#pragma unroll
            for (int o = 16; o; o >>= 1) qq += __shfl_xor_sync(0xffffffffu, qq, o);
            float inv = rsqrtf(qq * 0.0078125f + 1e-5f);
            __half2 p0 = __floats2half2_rn(d0 * inv * gg.x + bb.x, d1 * inv * gg.y + bb.y);
            __half2 p1 = __floats2half2_rn(d2 * inv * gg.z + bb.z, d3 * inv * gg.w + bb.w);
            uint2 P;
            P.x = *(const uint32_t*)&p0;
            P.y = *(const uint32_t*)&p1;
            *(uint2*)(a_sm + row * SMSB + lane * 8) = P;
        }
    }
    __syncthreads();

    float acc2[2][4][4];
#pragma unroll
    for (int mt = 0; mt < 2; mt++)
#pragma unroll
        for (int nt = 0; nt < 4; nt++)
#pragma unroll
            for (int j = 0; j < 4; j++) acc2[mt][nt][j] = 0.0f;

#pragma unroll
    for (int h = 0; h < 2; h++) {
        CPA_WAIT(1);  // h=0: G1 (w1=W1h0); h=1: G3 (w1=W1h1)
        __syncthreads();
#pragma unroll
        for (int mt = 0; mt < 2; mt++)
#pragma unroll
            for (int nt = 0; nt < 4; nt++)
#pragma unroll
                for (int j = 0; j < 4; j++) acc1[mt][nt][j] = 0.0f;
        compute_tile16(acc1, sb, s_w1, wm, wn, lane);
        __syncthreads();
        if (h == 0) {
            for (int i = tid * 16; i < TILEB; i += 8192) cpa16(s_w1 + i, W1 + TILEB + i);
            CPA_COMMIT();
        }
        // silu -> t_sm (fp16)
#pragma unroll
        for (int mt = 0; mt < 2; mt++)
#pragma unroll
            for (int nt = 0; nt < 4; nt++) {
                int row0 = wm * 32 + mt * 16 + q;
                int col = wn * 32 + nt * 8 + t2;
#pragma unroll
                for (int half = 0; half < 2; half++) {
                    float s0 = acc1[mt][nt][half * 2 + 0];
                    float s1 = acc1[mt][nt][half * 2 + 1];
                    s0 = s0 / (1.0f + expf(-s0));
                    s1 = s1 / (1.0f + expf(-s1));
                    __half2 p = __floats2half2_rn(s0, s1);
                    *(uint32_t*)(smem + 3 * TILEB + (row0 + half * 8) * SMSB + col * 2) =
                        *(const uint32_t*)&p;
                }
            }
        if (h == 0) CPA_WAIT(1); else CPA_WAIT(0);  // W2 chunk in w0
        __syncthreads();
        compute_tile16(acc2, s_t, s_w0, wm, wn, lane);
        __syncthreads();
        if (h == 0) {
            for (int i = tid; i < 128 * 16; i += 512) {
                int n = i >> 4, j = i & 15;
                cpa16(s_w0 + n * SMSB + j * 16, W2 + (size_t)n * 528 + 256 + j * 16);
            }
            CPA_COMMIT();
        }
    }

    // epilogue: out = x_sm (x2) + acc2
#pragma unroll
    for (int mt = 0; mt < 2; mt++) {
#pragma unroll
        for (int half = 0; half < 2; half++) {
            int lrow = wm * 32 + mt * 16 + q + half * 8;
            int row = m0 + lrow;
            if (row >= M) continue;
#pragma unroll
            for (int nt = 0; nt < 4; nt++) {
                int col = wn * 32 + nt * 8 + t2;
                float2 rr = *(const float2*)(x_sm + lrow * 512 + col * 4);
                float o0 = acc2[mt][nt][half * 2 + 0] + rr.x;
                float o1 = acc2[mt][nt][half * 2 + 1] + rr.y;
                *(float2*)(out + (size_t)row * 128 + col) = make_float2(o0, o1);
            }
        }
    }
}

// ====== weight prep: all 10 weights, fp16, one launch ======
__global__ void prep_all(const float* w0, const float* w1, const float* w2,
                         const float* w3, const float* w4, const float* w5,
                         const float* w6, const float* w7, const float* w8,
                         const float* w9, char* __restrict__ ib) {
    int y = blockIdx.y;
    const float* W;
    int K = 128, N = 128;
    switch (y) {
        case 0: W = w0; break;
        case 1: W = w1; break;
        case 2: W = w2; break;
        case 3: W = w3; break;
        case 4: W = w4; break;
        case 5: W = w5; break;
        case 6: W = w6; N = 256; break;
        case 7: W = w7; N = 256; break;
        case 8: W = w8; K = 256; break;
        default: W = w9; K = 256; break;
    }
    int idx = blockIdx.x * 256 + threadIdx.x;
    if (idx >= K * N) return;
    int k = idx / N, n = idx % N;
    size_t off = (size_t)y * 81920 + ((size_t)n * (K + 8) + k) * 2;
    *(unsigned short*)(ib + off) = __half_as_ushort(__float2half_rn(W[idx]));
}

__global__ void zero2_kernel(float* __restrict__ a, size_t na,
                             float* __restrict__ bz, size_t nb) {
    size_t i = (size_t)blockIdx.x * blockDim.x + threadIdx.x;
    size_t st = (size_t)gridDim.x * blockDim.x;
    for (size_t k = i; k < na; k += st) a[k] = 0.0f;
    for (size_t k = i; k < nb; k += st) bz[k] = 0.0f;
}

// ================= launch =================
extern "C" void kernel_launch(void* const* d_in, const int* in_sizes, int n_in,
                              void* d_out, int out_size) {
    const float* node = (const float*)d_in[0];
    const float* edge = (const float*)d_in[1];
    const int*   eidx = (const int*)d_in[2];
    const float* Wq = (const float*)d_in[3];
    const float* Wk = (const float*)d_in[4];
    const float* Wv = (const float*)d_in[5];
    const float* We = (const float*)d_in[6];
    const float* Wo_n = (const float*)d_in[7];
    const float* bo_n = (const float*)d_in[8];
    const float* Wo_e = (const float*)d_in[9];
    const float* bo_e = (const float*)d_in[10];
    const float* W1n = (const float*)d_in[11];
    const float* W2n = (const float*)d_in[12];
    const float* W1e = (const float*)d_in[13];
    const float* W2e = (const float*)d_in[14];
    const float* g1n = (const float*)d_in[15];
    const float* b1n = (const float*)d_in[16];
    const float* g1e = (const float*)d_in[17];
    const float* b1e = (const float*)d_in[18];
    const float* g2n = (const float*)d_in[19];
    const float* b2n = (const float*)d_in[20];
    const float* g2e = (const float*)d_in[21];
    const float* b2e = (const float*)d_in[22];

    const int N = in_sizes[0] / 128;
    const int E = in_sizes[1] / 128;
    float* out = (float*)d_out;

    __half *Q, *Kb, *Vb, *PE;
    float *wV, *z;
    char* wim;
    cudaGetSymbolAddress((void**)&Q, g_Q);
    cudaGetSymbolAddress((void**)&Kb, g_Kb);
    cudaGetSymbolAddress((void**)&Vb, g_Vb);
    cudaGetSymbolAddress((void**)&PE, g_PE);
    cudaGetSymbolAddress((void**)&wV, g_wV);
    cudaGetSymbolAddress((void**)&z, g_z);
    cudaGetSymbolAddress((void**)&wim, g_wimg);

    auto IM = [&](int i) { return wim + (size_t)i * 81920; };

    const int SMG = 2 * TILEB;             // 69632
    const int SMO = 4 * TILEB + 65536;     // 204800
    cudaFuncSetAttribute((const void*)proj_gemm_all, cudaFuncAttributeMaxDynamicSharedMemorySize, SMG);
    cudaFuncSetAttribute((const void*)out_ffn_all, cudaFuncAttributeMaxDynamicSharedMemorySize, SMO);

    const int TtN = (N + 127) / 128;
    const int TtE = (E + 127) / 128;

    // 0) weight images + accumulator zeroing
    prep_all<<<dim3(128, 10), 256>>>(Wq, Wk, Wv, We, Wo_n, Wo_e, W1n, W1e, W2n, W2e, wim);
    zero2_kernel<<<2048, 256>>>(wV, (size_t)N * 128, z, (size_t)N * 8);

    // 1) merged projections: LN1+QKV (node) and LN1e+PE (edge), 512 threads occ2
    proj_gemm_all<<<3 * TtN + TtE, 512, SMG>>>(TtN, node, edge, g1n, b1n, g1e, b1e,
                                               IM(0), Q, Kb, Vb, PE, N, E);

    // 2) per-edge attention + aggregation (warp-per-edge, coalesced)
    edge_kernel<<<(E + 7) / 8, 256>>>(Q, Kb, Vb, PE, eidx, wV, z, E);

    // 3) merged fused output chains (node tiles first, then edge tiles), 512 threads
    out_ffn_all<<<TtN + TtE, 512, SMO>>>(TtN, N, E, wV, z, PE,
                                         IM(4), IM(5), bo_n, bo_e, node, edge,
                                         IM(6), IM(7), IM(8), IM(9),
                                         g2n, b2n, g2e, b2e, out);
}

// round 14
// speedup vs baseline: 1.5071x; 1.1959x over previous
#include <cuda_runtime.h>
#include <cuda_fp16.h>
#include <math.h>
#include <stdint.h>

// ================= scratch (device globals) =================
#define NMAX 50000
#define EMAX 400000

__device__ __half g_Q [(size_t)NMAX * 128];
__device__ __half g_Kb[(size_t)NMAX * 128];
__device__ __half g_Vb[(size_t)NMAX * 128];
__device__ __half g_PE[(size_t)EMAX * 128];   // PE -> overwritten with e_attn
__device__ float g_wV [(size_t)NMAX * 128];
__device__ float g_z  [(size_t)NMAX * 8];
// weight images: [n][k] fp16, k padded by 8; 10 slots x 80KB
__device__ char g_wimg[10][81920];

#define SMSB 272  // smem k-stride in bytes (136 fp16)
#define TILEB (128 * SMSB)

// ================= PTX helpers =================
__device__ __forceinline__ uint32_t smem_u32(const void* p) {
    uint32_t a;
    asm("{ .reg .u64 t; cvta.to.shared.u64 t, %1; cvt.u32.u64 %0, t; }" : "=r"(a) : "l"(p));
    return a;
}
__device__ __forceinline__ void cpa16(uint32_t d, const void* s) {
    asm volatile("cp.async.cg.shared.global [%0], [%1], 16;" :: "r"(d), "l"(s));
}
#define CPA_COMMIT() asm volatile("cp.async.commit_group;" ::: "memory")
#define CPA_WAIT(n)  asm volatile("cp.async.wait_group %0;" :: "n"(n) : "memory")

__device__ __forceinline__ void red_add_v4(float* p, float a, float b, float c, float d) {
    asm volatile("red.global.add.v4.f32 [%0], {%1, %2, %3, %4};"
                 :: "l"(p), "f"(a), "f"(b), "f"(c), "f"(d) : "memory");
}
__device__ __forceinline__ void red_add_f(float* p, float a) {
    asm volatile("red.global.add.f32 [%0], %1;" :: "l"(p), "f"(a) : "memory");
}

__device__ __forceinline__ void mma_f16b(float* c, const uint32_t* a,
                                         uint32_t b0, uint32_t b1) {
    asm volatile(
        "mma.sync.aligned.m16n8k16.row.col.f32.f16.f16.f32 "
        "{%0,%1,%2,%3}, {%4,%5,%6,%7}, {%8,%9}, {%0,%1,%2,%3};"
        : "+f"(c[0]), "+f"(c[1]), "+f"(c[2]), "+f"(c[3])
        : "r"(a[0]), "r"(a[1]), "r"(a[2]), "r"(a[3]), "r"(b0), "r"(b1));
}
__device__ __forceinline__ void ldsm_x4(uint32_t* r, uint32_t addr) {
    asm volatile("ldmatrix.sync.aligned.m8n8.x4.shared.b16 {%0,%1,%2,%3}, [%4];"
                 : "=r"(r[0]), "=r"(r[1]), "=r"(r[2]), "=r"(r[3]) : "r"(addr));
}

// ---- 16-warp (4x4, warp tile 32x32) ldmatrix tile compute ----
__device__ __forceinline__ void compute_tile16(float (&acc)[2][4][4],
                                               uint32_t a_u32, uint32_t b_u32,
                                               int wm, int wn, int lane) {
    const int r = lane & 7, frag = lane >> 3;
    const int fr8 = (frag & 1) * 8, fc16 = (frag >> 1) * 16;
    uint32_t aaddr0 = a_u32 + (wm * 32 + fr8 + r) * SMSB + fc16;
    uint32_t aaddr1 = aaddr0 + 16 * SMSB;
    uint32_t baddr0 = b_u32 + (wn * 32 + (frag >> 1) * 8 + r) * SMSB + (frag & 1) * 16;
    uint32_t baddr1 = baddr0 + 16 * SMSB;
#pragma unroll
    for (int ks = 0; ks < 8; ks++) {
        uint32_t av0[4], av1[4], bv0[4], bv1[4];
        ldsm_x4(av0, aaddr0 + ks * 32);
        ldsm_x4(av1, aaddr1 + ks * 32);
        ldsm_x4(bv0, baddr0 + ks * 32);
        ldsm_x4(bv1, baddr1 + ks * 32);
        mma_f16b(acc[0][0], av0, bv0[0], bv0[1]);
        mma_f16b(acc[0][1], av0, bv0[2], bv0[3]);
        mma_f16b(acc[0][2], av0, bv1[0], bv1[1]);
        mma_f16b(acc[0][3], av0, bv1[2], bv1[3]);
        mma_f16b(acc[1][0], av1, bv0[0], bv0[1]);
        mma_f16b(acc[1][1], av1, bv0[2], bv0[3]);
        mma_f16b(acc[1][2], av1, bv1[0], bv1[1]);
        mma_f16b(acc[1][3], av1, bv1[2], bv1[3]);
    }
}

// ---- 8-warp (2x4, warp tile 64x32) ldmatrix tile compute ----
__device__ __forceinline__ void compute_tile8(float (&acc)[4][4][4],
                                              uint32_t a_u32, uint32_t b_u32,
                                              int wm, int wn, int lane) {
    const int r = lane & 7, frag = lane >> 3;
    const int fr8 = (frag & 1) * 8, fc16 = (frag >> 1) * 16;
    uint32_t aaddr[4];
#pragma unroll
    for (int mt = 0; mt < 4; mt++)
        aaddr[mt] = a_u32 + (wm * 64 + mt * 16 + fr8 + r) * SMSB + fc16;
    uint32_t baddr0 = b_u32 + (wn * 32 + (frag >> 1) * 8 + r) * SMSB + (frag & 1) * 16;
    uint32_t baddr1 = baddr0 + 16 * SMSB;
#pragma unroll
    for (int ks = 0; ks < 8; ks++) {
        uint32_t av[4][4], bv0[4], bv1[4];
        ldsm_x4(bv0, baddr0 + ks * 32);
        ldsm_x4(bv1, baddr1 + ks * 32);
#pragma unroll
        for (int mt = 0; mt < 4; mt++) ldsm_x4(av[mt], aaddr[mt] + ks * 32);
#pragma unroll
        for (int mt = 0; mt < 4; mt++) {
            mma_f16b(acc[mt][0], av[mt], bv0[0], bv0[1]);
            mma_f16b(acc[mt][1], av[mt], bv0[2], bv0[3]);
            mma_f16b(acc[mt][2], av[mt], bv1[0], bv1[1]);
            mma_f16b(acc[mt][3], av[mt], bv1[2], bv1[3]);
        }
    }
}

// A-load (rows of 128 fp32 -> fp16). ALOAD: 1 LN(P1=g,P2=b), 2 div-by-z(P1=z)
template <int ALOAD, int NT>
__device__ __forceinline__ void load_A(const float* __restrict__ A,
                                       const float* __restrict__ P1,
                                       const float* __restrict__ P2,
                                       int M, int m0, char* a_sm, int tid) {
    const int lane = tid & 31;
    float4 gg, bb;
    if (ALOAD == 1) {
        gg = *(const float4*)(P1 + lane * 4);
        bb = *(const float4*)(P2 + lane * 4);
    }
#pragma unroll 4
    for (int i = tid; i < 4096; i += NT) {
        int row = i >> 5;
        float4 v = make_float4(0.f, 0.f, 0.f, 0.f);
        bool valid = (m0 + row < M);
        if (valid) v = *(const float4*)(A + (size_t)(m0 + row) * 128 + lane * 4);
        if (ALOAD == 1) {
            float s = v.x + v.y + v.z + v.w;
#pragma unroll
            for (int o = 16; o; o >>= 1) s += __shfl_xor_sync(0xffffffffu, s, o);
            float mu = s * 0.0078125f;
            float d0 = v.x - mu, d1 = v.y - mu, d2 = v.z - mu, d3 = v.w - mu;
            float qq = d0 * d0 + d1 * d1 + d2 * d2 + d3 * d3;
#pragma unroll
            for (int o = 16; o; o >>= 1) qq += __shfl_xor_sync(0xffffffffu, qq, o);
            float inv = rsqrtf(qq * 0.0078125f + 1e-5f);
            v.x = d0 * inv * gg.x + bb.x;
            v.y = d1 * inv * gg.y + bb.y;
            v.z = d2 * inv * gg.z + bb.z;
            v.w = d3 * inv * gg.w + bb.w;
        } else if (ALOAD == 2) {
            float zz = valid ? P1[(size_t)(m0 + row) * 8 + (lane >> 2)] : 1.0f;
            float inv = 1.0f / (zz + 1e-6f);
            v.x *= inv; v.y *= inv; v.z *= inv; v.w *= inv;
        }
        __half2 p0 = __floats2half2_rn(v.x, v.y);
        __half2 p1 = __floats2half2_rn(v.z, v.w);
        uint2 P;
        P.x = *(const uint32_t*)&p0;
        P.y = *(const uint32_t*)&p1;
        *(uint2*)(a_sm + row * SMSB + lane * 8) = P;
    }
}

// ======= merged projection GEMM: QKV (node, slots 0-2) + PE (edge, slot 3) =======
__global__ __launch_bounds__(512, 2)
void proj_gemm_all(int TtN, const float* __restrict__ nodef,
                   const float* __restrict__ edgef, const float* __restrict__ g1n,
                   const float* __restrict__ b1n, const float* __restrict__ g1e,
                   const float* __restrict__ b1e, const char* __restrict__ WimgBase,
                   __half* __restrict__ Q, __half* __restrict__ Kb,
                   __half* __restrict__ Vb, __half* __restrict__ PE,
                   int Nn, int Ee) {
    extern __shared__ char smem[];
    char* a_sm = smem;
    const uint32_t sb = smem_u32(smem);
    const uint32_t sb_b = sb + TILEB;

    const int tid = threadIdx.x, wid = tid >> 5, lane = tid & 31;
    const int wm = wid >> 2, wn = wid & 3;
    const int q = lane >> 2, t2 = (lane & 3) * 2;

    const int bid = blockIdx.x;
    const bool is_edge = (bid >= 3 * TtN);
    const int slot = is_edge ? 3 : (bid / TtN);
    const int m0 = (is_edge ? (bid - 3 * TtN) : (bid % TtN)) * 128;
    const int M = is_edge ? Ee : Nn;
    const float* A = is_edge ? edgef : nodef;
    const float* g = is_edge ? g1e : g1n;
    const float* b = is_edge ? b1e : b1n;
    __half* C = (slot == 0) ? Q : (slot == 1) ? Kb : (slot == 2) ? Vb : PE;
    const char* Bg = WimgBase + (size_t)slot * 81920;

    for (int i = tid * 16; i < TILEB; i += 8192) cpa16(sb_b + i, Bg + i);
    CPA_COMMIT();

    float acc[2][4][4];
#pragma unroll
    for (int mt = 0; mt < 2; mt++)
#pragma unroll
        for (int nt = 0; nt < 4; nt++)
#pragma unroll
            for (int j = 0; j < 4; j++) acc[mt][nt][j] = 0.0f;

    load_A<1, 512>(A, g, b, M, m0, a_sm, tid);
    CPA_WAIT(0);
    __syncthreads();
    compute_tile16(acc, sb, sb_b, wm, wn, lane);

#pragma unroll
    for (int mt = 0; mt < 2; mt++) {
#pragma unroll
        for (int half = 0; half < 2; half++) {
            int row = m0 + wm * 32 + mt * 16 + q + half * 8;
            if (row >= M) continue;
#pragma unroll
            for (int nt = 0; nt < 4; nt++) {
                int col = wn * 32 + nt * 8 + t2;
                __half2 hp = __floats2half2_rn(acc[mt][nt][half * 2 + 0],
                                               acc[mt][nt][half * 2 + 1]);
                *(uint32_t*)((char*)C + ((size_t)row * 128 + col) * 2) =
                    *(const uint32_t*)&hp;
            }
        }
    }
}

// ================= per-edge attention (one warp per edge, fp16 tensors) =================
__global__ void edge_kernel(const __half* __restrict__ Q, const __half* __restrict__ K,
                            const __half* __restrict__ V, __half* __restrict__ PE,
                            const int* __restrict__ eidx, float* __restrict__ wV,
                            float* __restrict__ z, int E) {
    int e = blockIdx.x * 8 + (threadIdx.x >> 5);
    if (e >= E) return;
    int lane = threadIdx.x & 31;
    int src = eidx[e];
    int dst = eidx[E + e];
    int i = lane * 4;
    uint2 ku = *(const uint2*)(K + (size_t)src * 128 + i);
    uint2 qu = *(const uint2*)(Q + (size_t)dst * 128 + i);
    uint2 pu = *(const uint2*)(PE + (size_t)e * 128 + i);
    float2 k0 = __half22float2(*(__half2*)&ku.x), k1 = __half22float2(*(__half2*)&ku.y);
    float2 q0 = __half22float2(*(__half2*)&qu.x), q1 = __half22float2(*(__half2*)&qu.y);
    float2 p0 = __half22float2(*(__half2*)&pu.x), p1 = __half22float2(*(__half2*)&pu.y);
    const float sc = 0.25f;
    float s0 = fminf(fmaxf(k0.x * q0.x * sc, -5.0f), 5.0f) * p0.x;
    float s1 = fminf(fmaxf(k0.y * q0.y * sc, -5.0f), 5.0f) * p0.y;
    float s2 = fminf(fmaxf(k1.x * q1.x * sc, -5.0f), 5.0f) * p1.x;
    float s3 = fminf(fmaxf(k1.y * q1.y * sc, -5.0f), 5.0f) * p1.y;
    __half2 e0 = __floats2half2_rn(s0, s1), e1 = __floats2half2_rn(s2, s3);
    uint2 eo;
    eo.x = *(const uint32_t*)&e0;
    eo.y = *(const uint32_t*)&e1;
    *(uint2*)(PE + (size_t)e * 128 + i) = eo;

    float hs = s0 + s1 + s2 + s3;
    hs += __shfl_xor_sync(0xffffffffu, hs, 1);
    hs += __shfl_xor_sync(0xffffffffu, hs, 2);
    float w = expf(fminf(fmaxf(hs, -5.0f), 5.0f));

    uint2 vu = *(const uint2*)(V + (size_t)src * 128 + i);
    float2 v0 = __half22float2(*(__half2*)&vu.x), v1 = __half22float2(*(__half2*)&vu.y);
    red_add_v4(wV + (size_t)dst * 128 + i, v0.x * w, v0.y * w, v1.x * w, v1.y * w);
    if ((lane & 3) == 0)
        red_add_f(z + (size_t)dst * 8 + (lane >> 2), w);
}

// ====== fused output chain, occ-2 version (256 threads, 3 smem buffers + stats) ======
// out = x2 + FFN(LN2(x2)),  x2 = R + bias + op(A)@Wo.  x2 round-trips through out.
__global__ __launch_bounds__(256, 2)
void out_ffn_all(int TtN, int Nn, int Ee, const float* __restrict__ wV,
                 const float* __restrict__ z, const __half* __restrict__ eattn,
                 const char* __restrict__ WoN, const char* __restrict__ WoE,
                 const float* __restrict__ boN, const float* __restrict__ boE,
                 const float* __restrict__ nodeR, const float* __restrict__ edgeR,
                 const char* __restrict__ W1N, const char* __restrict__ W1E,
                 const char* __restrict__ W2N, const char* __restrict__ W2E,
                 const float* __restrict__ gN, const float* __restrict__ bN,
                 const float* __restrict__ gE, const float* __restrict__ bE,
                 float* __restrict__ outBase) {
    extern __shared__ char smem[];
    const uint32_t sb = smem_u32(smem);
    const uint32_t B0 = sb, B1 = sb + TILEB, B2 = sb + 2 * TILEB;
    char* b0c = smem;
    char* b1c = smem + TILEB;
    char* b2c = smem + 2 * TILEB;
    float* stats = (float*)(smem + 3 * TILEB);  // [128][4][2]

    const int tid = threadIdx.x, wid = tid >> 5, lane = tid & 31;
    const int wm = wid >> 2, wn = wid & 3;   // 2x4 warp grid, warp tile 64x32
    const int q = lane >> 2, t2 = (lane & 3) * 2;

    const bool is_edge = ((int)blockIdx.x >= TtN);
    const int m0 = (is_edge ? (blockIdx.x - TtN) : blockIdx.x) * 128;
    const int M = is_edge ? Ee : Nn;
    const char* Wo = is_edge ? WoE : WoN;
    const float* bias = is_edge ? boE : boN;
    const float* R = is_edge ? edgeR : nodeR;
    const char* W1 = is_edge ? W1E : W1N;
    const char* W2 = is_edge ? W2E : W2N;
    const float* g = is_edge ? gE : gN;
    const float* b = is_edge ? bE : bN;
    float* out = is_edge ? (outBase + (size_t)Nn * 128) : outBase;

    // G0: Wo -> B1 (+edge: A -> B0)
    for (int i = tid * 16; i < TILEB; i += 4096) cpa16(B1 + i, Wo + i);
    if (is_edge) {
        for (int i = tid; i < 2048; i += 256) {
            int row = i >> 4, j = i & 15;
            if (m0 + row < M)
                cpa16(B0 + row * SMSB + j * 16,
                      (const char*)eattn + (size_t)(m0 + row) * 256 + j * 16);
        }
    }
    CPA_COMMIT();
    // G1: W1 half0 -> B2
    for (int i = tid * 16; i < TILEB; i += 4096) cpa16(B2 + i, W1 + i);
    CPA_COMMIT();

    if (!is_edge) load_A<2, 256>(wV, z, nullptr, M, m0, b0c, tid);

    float acc[4][4][4];
#pragma unroll
    for (int mt = 0; mt < 4; mt++)
#pragma unroll
        for (int nt = 0; nt < 4; nt++)
#pragma unroll
            for (int j = 0; j < 4; j++) acc[mt][nt][j] = 0.0f;

    CPA_WAIT(1);  // G0 done
    __syncthreads();
    compute_tile8(acc, B0, B1, wm, wn, lane);  // op(A) @ Wo
    __syncthreads();                           // all done reading B0, B1
    // G2: W1 half1 -> B0 (overlaps x2/LN phase)
    for (int i = tid * 16; i < TILEB; i += 4096) cpa16(B0 + i, W1 + TILEB + i);
    CPA_COMMIT();

    // x2 phase: acc := x2 = acc + bias + R; store x2 -> out; row stats -> smem
#pragma unroll
    for (int mt = 0; mt < 4; mt++) {
#pragma unroll
        for (int half = 0; half < 2; half++) {
            int lrow = wm * 64 + mt * 16 + q + half * 8;
            int grow = m0 + lrow;
            bool valid = (grow < M);
            float s = 0.0f, ss = 0.0f;
#pragma unroll
            for (int nt = 0; nt < 4; nt++) {
                int col = wn * 32 + nt * 8 + t2;
                float2 bbv = *(const float2*)(bias + col);
                float2 rr = valid ? *(const float2*)(R + (size_t)grow * 128 + col)
                                  : make_float2(0.f, 0.f);
                float a0 = acc[mt][nt][half * 2 + 0] + bbv.x + rr.x;
                float a1 = acc[mt][nt][half * 2 + 1] + bbv.y + rr.y;
                acc[mt][nt][half * 2 + 0] = a0;
                acc[mt][nt][half * 2 + 1] = a1;
                if (valid)
                    *(float2*)(out + (size_t)grow * 128 + col) = make_float2(a0, a1);
                s += a0 + a1;
                ss += a0 * a0 + a1 * a1;
            }
            s += __shfl_xor_sync(0xffffffffu, s, 1);
            s += __shfl_xor_sync(0xffffffffu, s, 2);
            ss += __shfl_xor_sync(0xffffffffu, ss, 1);
            ss += __shfl_xor_sync(0xffffffffu, ss, 2);
            if ((lane & 3) == 0) {
                stats[(lrow * 4 + wn) * 2 + 0] = s;
                stats[(lrow * 4 + wn) * 2 + 1] = ss;
            }
        }
    }
    __syncthreads();  // stats visible

    // LN2 from register x2 -> fp16 xn into B1 (Wo dead)
#pragma unroll
    for (int mt = 0; mt < 4; mt++) {
#pragma unroll
        for (int half = 0; half < 2; half++) {
            int lrow = wm * 64 + mt * 16 + q + half * 8;
            float s = 0.0f, ss = 0.0f;
#pragma unroll
            for (int w4 = 0; w4 < 4; w4++) {
                s += stats[(lrow * 4 + w4) * 2 + 0];
                ss += stats[(lrow * 4 + w4) * 2 + 1];
            }
            float mu = s * 0.0078125f;
            float var = ss * 0.0078125f - mu * mu;
            float inv = rsqrtf(var + 1e-5f);
#pragma unroll
            for (int nt = 0; nt < 4; nt++) {
                int col = wn * 32 + nt * 8 + t2;
                float2 gg = *(const float2*)(g + col);
                float2 bbv = *(const float2*)(b + col);
                float h0 = (acc[mt][nt][half * 2 + 0] - mu) * inv * gg.x + bbv.x;
                float h1 = (acc[mt][nt][half * 2 + 1] - mu) * inv * gg.y + bbv.y;
                __half2 p = __floats2half2_rn(h0, h1);
                *(uint32_t*)(b1c + lrow * SMSB + col * 2) = *(const uint32_t*)&p;
            }
        }
    }
    CPA_WAIT(1);      // G1 done (W1h0 in B2); G2 may be in flight
    __syncthreads();  // xn visible

    float acc1[4][4][4];
#pragma unroll
    for (int mt = 0; mt < 4; mt++)
#pragma unroll
        for (int nt = 0; nt < 4; nt++)
#pragma unroll
            for (int j = 0; j < 4; j++) acc1[mt][nt][j] = 0.0f;
    compute_tile8(acc1, B1, B2, wm, wn, lane);  // xn @ W1h0
    __syncthreads();                            // done reading B2

    // silu -> t0 into B2 (W1h0 dead)
#pragma unroll
    for (int mt = 0; mt < 4; mt++)
#pragma unroll
        for (int nt = 0; nt < 4; nt++) {
            int row0 = wm * 64 + mt * 16 + q;
            int col = wn * 32 + nt * 8 + t2;
#pragma unroll
            for (int half = 0; half < 2; half++) {
                float s0 = acc1[mt][nt][half * 2 + 0];
                float s1 = acc1[mt][nt][half * 2 + 1];
                s0 = s0 / (1.0f + expf(-s0));
                s1 = s1 / (1.0f + expf(-s1));
                __half2 p = __floats2half2_rn(s0, s1);
                *(uint32_t*)(b2c + (row0 + half * 8) * SMSB + col * 2) =
                    *(const uint32_t*)&p;
            }
        }
    CPA_WAIT(0);      // G2 done (W1h1 in B0)
    __syncthreads();  // t0 visible

#pragma unroll
    for (int mt = 0; mt < 4; mt++)
#pragma unroll
        for (int nt = 0; nt < 4; nt++)
#pragma unroll
            for (int j = 0; j < 4; j++) acc1[mt][nt][j] = 0.0f;
    compute_tile8(acc1, B1, B0, wm, wn, lane);  // xn @ W1h1
    __syncthreads();                            // done reading B0, B1(xn dead)

    // G3: W2 chunk0 -> B0
    for (int i = tid; i < 2048; i += 256) {
        int n = i >> 4, j = i & 15;
        cpa16(B0 + n * SMSB + j * 16, W2 + (size_t)n * 528 + j * 16);
    }
    CPA_COMMIT();
    // silu -> t1 into B1
#pragma unroll
    for (int mt = 0; mt < 4; mt++)
#pragma unroll
        for (int nt = 0; nt < 4; nt++) {
            int row0 = wm * 64 + mt * 16 + q;
            int col = wn * 32 + nt * 8 + t2;
#pragma unroll
            for (int half = 0; half < 2; half++) {
                float s0 = acc1[mt][nt][half * 2 + 0];
                float s1 = acc1[mt][nt][half * 2 + 1];
                s0 = s0 / (1.0f + expf(-s0));
                s1 = s1 / (1.0f + expf(-s1));
                __half2 p = __floats2half2_rn(s0, s1);
                *(uint32_t*)(b1c + (row0 + half * 8) * SMSB + col * 2) =
                    *(const uint32_t*)&p;
            }
        }
    CPA_WAIT(0);
    __syncthreads();  // W2c0 + t1 visible

    float acc2[4][4][4];
#pragma unroll
    for (int mt = 0; mt < 4; mt++)
#pragma unroll
        for (int nt = 0; nt < 4; nt++)
#pragma unroll
            for (int j = 0; j < 4; j++) acc2[mt][nt][j] = 0.0f;
    compute_tile8(acc2, B2, B0, wm, wn, lane);  // t0 @ W2c0
    __syncthreads();                            // done reading B0

    // G4: W2 chunk1 -> B0
    for (int i = tid; i < 2048; i += 256) {
        int n = i >> 4, j = i & 15;
        cpa16(B0 + n * SMSB + j * 16, W2 + (size_t)n * 528 + 256 + j * 16);
    }
    CPA_COMMIT();
    CPA_WAIT(0);
    __syncthreads();
    compute_tile8(acc2, B1, B0, wm, wn, lane);  // t1 @ W2c1 (accumulate)

    // epilogue: out = x2 (reload from out) + acc2
#pragma unroll
    for (int mt = 0; mt < 4; mt++) {
#pragma unroll
        for (int half = 0; half < 2; half++) {
            int grow = m0 + wm * 64 + mt * 16 + q + half * 8;
            if (grow >= M) continue;
#pragma unroll
            for (int nt = 0; nt < 4; nt++) {
                int col = wn * 32 + nt * 8 + t2;
                float2 x2 = *(const float2*)(out + (size_t)grow * 128 + col);
                float o0 = acc2[mt][nt][half * 2 + 0] + x2.x;
                float o1 = acc2[mt][nt][half * 2 + 1] + x2.y;
                *(float2*)(out + (size_t)grow * 128 + col) = make_float2(o0, o1);
            }
        }
    }
}

// ====== weight prep: all 10 weights, fp16, one launch ======
__global__ void prep_all(const float* w0, const float* w1, const float* w2,
                         const float* w3, const float* w4, const float* w5,
                         const float* w6, const float* w7, const float* w8,
                         const float* w9, char* __restrict__ ib) {
    int y = blockIdx.y;
    const float* W;
    int K = 128, N = 128;
    switch (y) {
        case 0: W = w0; break;
        case 1: W = w1; break;
        case 2: W = w2; break;
        case 3: W = w3; break;
        case 4: W = w4; break;
        case 5: W = w5; break;
        case 6: W = w6; N = 256; break;
        case 7: W = w7; N = 256; break;
        case 8: W = w8; K = 256; break;
        default: W = w9; K = 256; break;
    }
    int idx = blockIdx.x * 256 + threadIdx.x;
    if (idx >= K * N) return;
    int k = idx / N, n = idx % N;
    size_t off = (size_t)y * 81920 + ((size_t)n * (K + 8) + k) * 2;
    *(unsigned short*)(ib + off) = __half_as_ushort(__float2half_rn(W[idx]));
}

__global__ void zero2_kernel(float* __restrict__ a, size_t na,
                             float* __restrict__ bz, size_t nb) {
    size_t i = (size_t)blockIdx.x * blockDim.x + threadIdx.x;
    size_t st = (size_t)gridDim.x * blockDim.x;
    for (size_t k = i; k < na; k += st) a[k] = 0.0f;
    for (size_t k = i; k < nb; k += st) bz[k] = 0.0f;
}

// ================= launch =================
extern "C" void kernel_launch(void* const* d_in, const int* in_sizes, int n_in,
                              void* d_out, int out_size) {
    const float* node = (const float*)d_in[0];
    const float* edge = (const float*)d_in[1];
    const int*   eidx = (const int*)d_in[2];
    const float* Wq = (const float*)d_in[3];
    const float* Wk = (const float*)d_in[4];
    const float* Wv = (const float*)d_in[5];
    const float* We = (const float*)d_in[6];
    const float* Wo_n = (const float*)d_in[7];
    const float* bo_n = (const float*)d_in[8];
    const float* Wo_e = (const float*)d_in[9];
    const float* bo_e = (const float*)d_in[10];
    const float* W1n = (const float*)d_in[11];
    const float* W2n = (const float*)d_in[12];
    const float* W1e = (const float*)d_in[13];
    const float* W2e = (const float*)d_in[14];
    const float* g1n = (const float*)d_in[15];
    const float* b1n = (const float*)d_in[16];
    const float* g1e = (const float*)d_in[17];
    const float* b1e = (const float*)d_in[18];
    const float* g2n = (const float*)d_in[19];
    const float* b2n = (const float*)d_in[20];
    const float* g2e = (const float*)d_in[21];
    const float* b2e = (const float*)d_in[22];

    const int N = in_sizes[0] / 128;
    const int E = in_sizes[1] / 128;
    float* out = (float*)d_out;

    __half *Q, *Kb, *Vb, *PE;
    float *wV, *z;
    char* wim;
    cudaGetSymbolAddress((void**)&Q, g_Q);
    cudaGetSymbolAddress((void**)&Kb, g_Kb);
    cudaGetSymbolAddress((void**)&Vb, g_Vb);
    cudaGetSymbolAddress((void**)&PE, g_PE);
    cudaGetSymbolAddress((void**)&wV, g_wV);
    cudaGetSymbolAddress((void**)&z, g_z);
    cudaGetSymbolAddress((void**)&wim, g_wimg);

    auto IM = [&](int i) { return wim + (size_t)i * 81920; };

    const int SMG = 2 * TILEB;           // 69632
    const int SMO = 3 * TILEB + 4096;    // 108544
    cudaFuncSetAttribute((const void*)proj_gemm_all, cudaFuncAttributeMaxDynamicSharedMemorySize, SMG);
    cudaFuncSetAttribute((const void*)out_ffn_all, cudaFuncAttributeMaxDynamicSharedMemorySize, SMO);

    const int TtN = (N + 127) / 128;
    const int TtE = (E + 127) / 128;

    // 0) weight images + accumulator zeroing
    prep_all<<<dim3(128, 10), 256>>>(Wq, Wk, Wv, We, Wo_n, Wo_e, W1n, W1e, W2n, W2e, wim);
    zero2_kernel<<<2048, 256>>>(wV, (size_t)N * 128, z, (size_t)N * 8);

    // 1) merged projections: LN1+QKV (node) and LN1e+PE (edge), 512 threads occ2
    proj_gemm_all<<<3 * TtN + TtE, 512, SMG>>>(TtN, node, edge, g1n, b1n, g1e, b1e,
                                               IM(0), Q, Kb, Vb, PE, N, E);

    // 2) per-edge attention + aggregation (warp-per-edge, coalesced)
    edge_kernel<<<(E + 7) / 8, 256>>>(Q, Kb, Vb, PE, eidx, wV, z, E);

    // 3) merged fused output chains, occ-2 (256 threads, 108.5KB smem)
    out_ffn_all<<<TtN + TtE, 256, SMO>>>(TtN, N, E, wV, z, PE,
                                         IM(4), IM(5), bo_n, bo_e, node, edge,
                                         IM(6), IM(7), IM(8), IM(9),
                                         g2n, b2n, g2e, b2e, out);
}

// round 15
// speedup vs baseline: 1.5365x; 1.0195x over previous
#include <cuda_runtime.h>
#include <cuda_fp16.h>
#include <math.h>
#include <stdint.h>

// ================= scratch (device globals) =================
#define NMAX 50000
#define EMAX 400000

__device__ __half g_Q [(size_t)NMAX * 128];
__device__ __half g_Kb[(size_t)NMAX * 128];
__device__ __half g_Vb[(size_t)NMAX * 128];
__device__ __half g_PE[(size_t)EMAX * 128];   // PE -> overwritten with e_attn
__device__ float g_wV [(size_t)NMAX * 128];
__device__ float g_z  [(size_t)NMAX * 8];
// weight images: [n][k] fp16, k padded by 8; 10 slots x 80KB
__device__ char g_wimg[10][81920];

#define SMSB 272  // smem k-stride in bytes (136 fp16)
#define TILEB (128 * SMSB)

// ================= PTX helpers =================
__device__ __forceinline__ uint32_t smem_u32(const void* p) {
    uint32_t a;
    asm("{ .reg .u64 t; cvta.to.shared.u64 t, %1; cvt.u32.u64 %0, t; }" : "=r"(a) : "l"(p));
    return a;
}
__device__ __forceinline__ void cpa16(uint32_t d, const void* s) {
    asm volatile("cp.async.cg.shared.global [%0], [%1], 16;" :: "r"(d), "l"(s));
}
#define CPA_COMMIT() asm volatile("cp.async.commit_group;" ::: "memory")
#define CPA_WAIT(n)  asm volatile("cp.async.wait_group %0;" :: "n"(n) : "memory")

__device__ __forceinline__ void red_add_v4(float* p, float a, float b, float c, float d) {
    asm volatile("red.global.add.v4.f32 [%0], {%1, %2, %3, %4};"
                 :: "l"(p), "f"(a), "f"(b), "f"(c), "f"(d) : "memory");
}
__device__ __forceinline__ void red_add_f(float* p, float a) {
    asm volatile("red.global.add.f32 [%0], %1;" :: "l"(p), "f"(a) : "memory");
}

__device__ __forceinline__ void mma_f16b(float* c, const uint32_t* a,
                                         uint32_t b0, uint32_t b1) {
    asm volatile(
        "mma.sync.aligned.m16n8k16.row.col.f32.f16.f16.f32 "
        "{%0,%1,%2,%3}, {%4,%5,%6,%7}, {%8,%9}, {%0,%1,%2,%3};"
        : "+f"(c[0]), "+f"(c[1]), "+f"(c[2]), "+f"(c[3])
        : "r"(a[0]), "r"(a[1]), "r"(a[2]), "r"(a[3]), "r"(b0), "r"(b1));
}
__device__ __forceinline__ void ldsm_x4(uint32_t* r, uint32_t addr) {
    asm volatile("ldmatrix.sync.aligned.m8n8.x4.shared.b16 {%0,%1,%2,%3}, [%4];"
                 : "=r"(r[0]), "=r"(r[1]), "=r"(r[2]), "=r"(r[3]) : "r"(addr));
}

// ---- 16-warp (4x4, warp tile 32x32) ldmatrix tile compute ----
__device__ __forceinline__ void compute_tile16(float (&acc)[2][4][4],
                                               uint32_t a_u32, uint32_t b_u32,
                                               int wm, int wn, int lane) {
    const int r = lane & 7, frag = lane >> 3;
    uint32_t aaddr0 = a_u32 + (wm * 32 + (frag & 1) * 8 + r) * SMSB + (frag >> 1) * 16;
    uint32_t aaddr1 = aaddr0 + 16 * SMSB;
    uint32_t baddr0 = b_u32 + (wn * 32 + (frag >> 1) * 8 + r) * SMSB + (frag & 1) * 16;
    uint32_t baddr1 = baddr0 + 16 * SMSB;
#pragma unroll
    for (int ks = 0; ks < 8; ks++) {
        uint32_t av0[4], av1[4], bv0[4], bv1[4];
        ldsm_x4(av0, aaddr0 + ks * 32);
        ldsm_x4(av1, aaddr1 + ks * 32);
        ldsm_x4(bv0, baddr0 + ks * 32);
        ldsm_x4(bv1, baddr1 + ks * 32);
        mma_f16b(acc[0][0], av0, bv0[0], bv0[1]);
        mma_f16b(acc[0][1], av0, bv0[2], bv0[3]);
        mma_f16b(acc[0][2], av0, bv1[0], bv1[1]);
        mma_f16b(acc[0][3], av0, bv1[2], bv1[3]);
        mma_f16b(acc[1][0], av1, bv0[0], bv0[1]);
        mma_f16b(acc[1][1], av1, bv0[2], bv0[3]);
        mma_f16b(acc[1][2], av1, bv1[0], bv1[1]);
        mma_f16b(acc[1][3], av1, bv1[2], bv1[3]);
    }
}

// ---- single m16-slice compute (8-warp layout, warp n-range 32): acc[4nt][4] ----
__device__ __forceinline__ void compute_mt(float (&acc)[4][4], uint32_t a_row_u32,
                                           uint32_t b_u32, int wn, int lane) {
    const int r = lane & 7, frag = lane >> 3;
    uint32_t aaddr = a_row_u32 + ((frag & 1) * 8 + r) * SMSB + (frag >> 1) * 16;
    uint32_t baddr0 = b_u32 + (wn * 32 + (frag >> 1) * 8 + r) * SMSB + (frag & 1) * 16;
    uint32_t baddr1 = baddr0 + 16 * SMSB;
#pragma unroll
    for (int ks = 0; ks < 8; ks++) {
        uint32_t av[4], bv0[4], bv1[4];
        ldsm_x4(av, aaddr + ks * 32);
        ldsm_x4(bv0, baddr0 + ks * 32);
        ldsm_x4(bv1, baddr1 + ks * 32);
        mma_f16b(acc[0], av, bv0[0], bv0[1]);
        mma_f16b(acc[1], av, bv0[2], bv0[3]);
        mma_f16b(acc[2], av, bv1[0], bv1[1]);
        mma_f16b(acc[3], av, bv1[2], bv1[3]);
    }
}

// A-load (rows of 128 fp32 -> fp16). ALOAD: 1 LN(P1=g,P2=b), 2 div-by-z(P1=z)
template <int ALOAD, int NT>
__device__ __forceinline__ void load_A(const float* __restrict__ A,
                                       const float* __restrict__ P1,
                                       const float* __restrict__ P2,
                                       int M, int m0, char* a_sm, int tid) {
    const int lane = tid & 31;
    float4 gg, bb;
    if (ALOAD == 1) {
        gg = *(const float4*)(P1 + lane * 4);
        bb = *(const float4*)(P2 + lane * 4);
    }
#pragma unroll 4
    for (int i = tid; i < 4096; i += NT) {
        int row = i >> 5;
        float4 v = make_float4(0.f, 0.f, 0.f, 0.f);
        bool valid = (m0 + row < M);
        if (valid) v = *(const float4*)(A + (size_t)(m0 + row) * 128 + lane * 4);
        if (ALOAD == 1) {
            float s = v.x + v.y + v.z + v.w;
#pragma unroll
            for (int o = 16; o; o >>= 1) s += __shfl_xor_sync(0xffffffffu, s, o);
            float mu = s * 0.0078125f;
            float d0 = v.x - mu, d1 = v.y - mu, d2 = v.z - mu, d3 = v.w - mu;
            float qq = d0 * d0 + d1 * d1 + d2 * d2 + d3 * d3;
#pragma unroll
            for (int o = 16; o; o >>= 1) qq += __shfl_xor_sync(0xffffffffu, qq, o);
            float inv = rsqrtf(qq * 0.0078125f + 1e-5f);
            v.x = d0 * inv * gg.x + bb.x;
            v.y = d1 * inv * gg.y + bb.y;
            v.z = d2 * inv * gg.z + bb.z;
            v.w = d3 * inv * gg.w + bb.w;
        } else if (ALOAD == 2) {
            float zz = valid ? P1[(size_t)(m0 + row) * 8 + (lane >> 2)] : 1.0f;
            float inv = 1.0f / (zz + 1e-6f);
            v.x *= inv; v.y *= inv; v.z *= inv; v.w *= inv;
        }
        __half2 p0 = __floats2half2_rn(v.x, v.y);
        __half2 p1 = __floats2half2_rn(v.z, v.w);
        uint2 P;
        P.x = *(const uint32_t*)&p0;
        P.y = *(const uint32_t*)&p1;
        *(uint2*)(a_sm + row * SMSB + lane * 8) = P;
    }
}

// ======= projections: node tiles do QKV (A loaded once, B ping-pong); edge tiles do PE =======
__global__ __launch_bounds__(512, 2)
void proj_gemm_all(int TtN, const float* __restrict__ nodef,
                   const float* __restrict__ edgef, const float* __restrict__ g1n,
                   const float* __restrict__ b1n, const float* __restrict__ g1e,
                   const float* __restrict__ b1e, const char* __restrict__ WimgBase,
                   __half* __restrict__ Q, __half* __restrict__ Kb,
                   __half* __restrict__ Vb, __half* __restrict__ PE,
                   int Nn, int Ee) {
    extern __shared__ char smem[];
    char* a_sm = smem;
    const uint32_t sb = smem_u32(smem);
    const uint32_t BB0 = sb + TILEB, BB1 = sb + 2 * TILEB;

    const int tid = threadIdx.x, wid = tid >> 5, lane = tid & 31;
    const int wm = wid >> 2, wn = wid & 3;
    const int q = lane >> 2, t2 = (lane & 3) * 2;

    const bool is_edge = ((int)blockIdx.x >= TtN);
    const int m0 = (is_edge ? (blockIdx.x - TtN) : blockIdx.x) * 128;
    const int M = is_edge ? Ee : Nn;
    const float* A = is_edge ? edgef : nodef;
    const float* g = is_edge ? g1e : g1n;
    const float* b = is_edge ? b1e : b1n;

    float acc[2][4][4];
    auto store_C = [&](__half* C) {
#pragma unroll
        for (int mt = 0; mt < 2; mt++) {
#pragma unroll
            for (int half = 0; half < 2; half++) {
                int row = m0 + wm * 32 + mt * 16 + q + half * 8;
                if (row >= M) continue;
#pragma unroll
                for (int nt = 0; nt < 4; nt++) {
                    int col = wn * 32 + nt * 8 + t2;
                    __half2 hp = __floats2half2_rn(acc[mt][nt][half * 2 + 0],
                                                   acc[mt][nt][half * 2 + 1]);
                    *(uint32_t*)((char*)C + ((size_t)row * 128 + col) * 2) =
                        *(const uint32_t*)&hp;
                }
            }
        }
    };
    auto zacc = [&]() {
#pragma unroll
        for (int mt = 0; mt < 2; mt++)
#pragma unroll
            for (int nt = 0; nt < 4; nt++)
#pragma unroll
                for (int j = 0; j < 4; j++) acc[mt][nt][j] = 0.0f;
    };

    if (is_edge) {
        for (int i = tid * 16; i < TILEB; i += 8192)
            cpa16(BB0 + i, WimgBase + 3 * 81920 + i);
        CPA_COMMIT();
        load_A<1, 512>(A, g, b, M, m0, a_sm, tid);
        CPA_WAIT(0);
        __syncthreads();
        zacc();
        compute_tile16(acc, sb, BB0, wm, wn, lane);
        store_C(PE);
        return;
    }

    // node: slots 0,1,2 with ping-pong B
    for (int i = tid * 16; i < TILEB; i += 8192) cpa16(BB0 + i, WimgBase + i);
    CPA_COMMIT();
    load_A<1, 512>(A, g, b, M, m0, a_sm, tid);
    for (int i = tid * 16; i < TILEB; i += 8192) cpa16(BB1 + i, WimgBase + 81920 + i);
    CPA_COMMIT();

    CPA_WAIT(1);  // slot0 done
    __syncthreads();
    zacc();
    compute_tile16(acc, sb, BB0, wm, wn, lane);
    store_C(Q);
    __syncthreads();  // BB0 reads done
    for (int i = tid * 16; i < TILEB; i += 8192) cpa16(BB0 + i, WimgBase + 2 * 81920 + i);
    CPA_COMMIT();

    CPA_WAIT(1);  // slot1 done
    __syncthreads();
    zacc();
    compute_tile16(acc, sb, BB1, wm, wn, lane);
    store_C(Kb);

    CPA_WAIT(0);  // slot2 done
    __syncthreads();
    zacc();
    compute_tile16(acc, sb, BB0, wm, wn, lane);
    store_C(Vb);
}

// ================= per-edge attention (one warp per edge, fp16 tensors) =================
__global__ void edge_kernel(const __half* __restrict__ Q, const __half* __restrict__ K,
                            const __half* __restrict__ V, __half* __restrict__ PE,
                            const int* __restrict__ eidx, float* __restrict__ wV,
                            float* __restrict__ z, int E) {
    int e = blockIdx.x * 8 + (threadIdx.x >> 5);
    if (e >= E) return;
    int lane = threadIdx.x & 31;
    int src = eidx[e];
    int dst = eidx[E + e];
    int i = lane * 4;
    uint2 ku = *(const uint2*)(K + (size_t)src * 128 + i);
    uint2 qu = *(const uint2*)(Q + (size_t)dst * 128 + i);
    uint2 pu = *(const uint2*)(PE + (size_t)e * 128 + i);
    float2 k0 = __half22float2(*(__half2*)&ku.x), k1 = __half22float2(*(__half2*)&ku.y);
    float2 q0 = __half22float2(*(__half2*)&qu.x), q1 = __half22float2(*(__half2*)&qu.y);
    float2 p0 = __half22float2(*(__half2*)&pu.x), p1 = __half22float2(*(__half2*)&pu.y);
    const float sc = 0.25f;
    float s0 = fminf(fmaxf(k0.x * q0.x * sc, -5.0f), 5.0f) * p0.x;
    float s1 = fminf(fmaxf(k0.y * q0.y * sc, -5.0f), 5.0f) * p0.y;
    float s2 = fminf(fmaxf(k1.x * q1.x * sc, -5.0f), 5.0f) * p1.x;
    float s3 = fminf(fmaxf(k1.y * q1.y * sc, -5.0f), 5.0f) * p1.y;
    __half2 e0 = __floats2half2_rn(s0, s1), e1 = __floats2half2_rn(s2, s3);
    uint2 eo;
    eo.x = *(const uint32_t*)&e0;
    eo.y = *(const uint32_t*)&e1;
    *(uint2*)(PE + (size_t)e * 128 + i) = eo;

    float hs = s0 + s1 + s2 + s3;
    hs += __shfl_xor_sync(0xffffffffu, hs, 1);
    hs += __shfl_xor_sync(0xffffffffu, hs, 2);
    float w = expf(fminf(fmaxf(hs, -5.0f), 5.0f));

    uint2 vu = *(const uint2*)(V + (size_t)src * 128 + i);
    float2 v0 = __half22float2(*(__half2*)&vu.x), v1 = __half22float2(*(__half2*)&vu.y);
    red_add_v4(wV + (size_t)dst * 128 + i, v0.x * w, v0.y * w, v1.x * w, v1.y * w);
    if ((lane & 3) == 0)
        red_add_f(z + (size_t)dst * 8 + (lane >> 2), w);
}

// ====== fused output chain, occ-2, x2 register-resident (MMA-seeded W2 accumulate) ======
// out = x2 + FFN(LN2(x2)),  x2 = R + bias + op(A)@Wo
__global__ __launch_bounds__(256, 2)
void out_ffn_all(int TtN, int Nn, int Ee, const float* __restrict__ wV,
                 const float* __restrict__ z, const __half* __restrict__ eattn,
                 const char* __restrict__ WoN, const char* __restrict__ WoE,
                 const float* __restrict__ boN, const float* __restrict__ boE,
                 const float* __restrict__ nodeR, const float* __restrict__ edgeR,
                 const char* __restrict__ W1N, const char* __restrict__ W1E,
                 const char* __restrict__ W2N, const char* __restrict__ W2E,
                 const float* __restrict__ gN, const float* __restrict__ bN,
                 const float* __restrict__ gE, const float* __restrict__ bE,
                 float* __restrict__ outBase) {
    extern __shared__ char smem[];
    const uint32_t sb = smem_u32(smem);
    const uint32_t B0 = sb, B1 = sb + TILEB, B2 = sb + 2 * TILEB;
    char* b0c = smem;
    char* b1c = smem + TILEB;
    char* b2c = smem + 2 * TILEB;
    float* stats = (float*)(smem + 3 * TILEB);  // [128][4][2]

    const int tid = threadIdx.x, wid = tid >> 5, lane = tid & 31;
    const int wm = wid >> 2, wn = wid & 3;   // 2x4 warp grid, warp tile 64x32
    const int q = lane >> 2, t2 = (lane & 3) * 2;

    const bool is_edge = ((int)blockIdx.x >= TtN);
    const int m0 = (is_edge ? (blockIdx.x - TtN) : blockIdx.x) * 128;
    const int M = is_edge ? Ee : Nn;
    const char* Wo = is_edge ? WoE : WoN;
    const float* bias = is_edge ? boE : boN;
    const float* R = is_edge ? edgeR : nodeR;
    const char* W1 = is_edge ? W1E : W1N;
    const char* W2 = is_edge ? W2E : W2N;
    const float* g = is_edge ? gE : gN;
    const float* b = is_edge ? bE : bN;
    float* out = is_edge ? (outBase + (size_t)Nn * 128) : outBase;

    // G0: Wo -> B1 (+edge: A -> B0); G1: W1 half0 -> B2
    for (int i = tid * 16; i < TILEB; i += 4096) cpa16(B1 + i, Wo + i);
    if (is_edge) {
        for (int i = tid; i < 2048; i += 256) {
            int row = i >> 4, j = i & 15;
            if (m0 + row < M)
                cpa16(B0 + row * SMSB + j * 16,
                      (const char*)eattn + (size_t)(m0 + row) * 256 + j * 16);
        }
    }
    CPA_COMMIT();
    for (int i = tid * 16; i < TILEB; i += 4096) cpa16(B2 + i, W1 + i);
    CPA_COMMIT();

    if (!is_edge) load_A<2, 256>(wV, z, nullptr, M, m0, b0c, tid);

    float acc[4][4][4];  // x2 -> final result (MMA-seeded)
#pragma unroll
    for (int mt = 0; mt < 4; mt++)
#pragma unroll
        for (int nt = 0; nt < 4; nt++)
#pragma unroll
            for (int j = 0; j < 4; j++) acc[mt][nt][j] = 0.0f;

    CPA_WAIT(1);  // G0 done
    __syncthreads();
#pragma unroll
    for (int mt = 0; mt < 4; mt++)
        compute_mt(acc[mt], B0 + (wm * 64 + mt * 16) * SMSB, B1, wn, lane);  // A@Wo
    __syncthreads();  // B0, B1 free

    // x2 = acc + bias + R (register-resident); stats -> smem
#pragma unroll
    for (int mt = 0; mt < 4; mt++) {
#pragma unroll
        for (int half = 0; half < 2; half++) {
            int lrow = wm * 64 + mt * 16 + q + half * 8;
            int grow = m0 + lrow;
            bool valid = (grow < M);
            float s = 0.0f, ss = 0.0f;
#pragma unroll
            for (int nt = 0; nt < 4; nt++) {
                int col = wn * 32 + nt * 8 + t2;
                float2 bbv = *(const float2*)(bias + col);
                float2 rr = valid ? *(const float2*)(R + (size_t)grow * 128 + col)
                                  : make_float2(0.f, 0.f);
                float a0 = acc[mt][nt][half * 2 + 0] + bbv.x + rr.x;
                float a1 = acc[mt][nt][half * 2 + 1] + bbv.y + rr.y;
                acc[mt][nt][half * 2 + 0] = a0;
                acc[mt][nt][half * 2 + 1] = a1;
                s += a0 + a1;
                ss += a0 * a0 + a1 * a1;
            }
            s += __shfl_xor_sync(0xffffffffu, s, 1);
            s += __shfl_xor_sync(0xffffffffu, s, 2);
            ss += __shfl_xor_sync(0xffffffffu, ss, 1);
            ss += __shfl_xor_sync(0xffffffffu, ss, 2);
            if ((lane & 3) == 0) {
                stats[(lrow * 4 + wn) * 2 + 0] = s;
                stats[(lrow * 4 + wn) * 2 + 1] = ss;
            }
        }
    }
    __syncthreads();  // stats visible

    // LN2 (x2 in regs) -> fp16 xn into B0
#pragma unroll
    for (int mt = 0; mt < 4; mt++) {
#pragma unroll
        for (int half = 0; half < 2; half++) {
            int lrow = wm * 64 + mt * 16 + q + half * 8;
            float s = 0.0f, ss = 0.0f;
#pragma unroll
            for (int w4 = 0; w4 < 4; w4++) {
                s += stats[(lrow * 4 + w4) * 2 + 0];
                ss += stats[(lrow * 4 + w4) * 2 + 1];
            }
            float mu = s * 0.0078125f;
            float var = ss * 0.0078125f - mu * mu;
            float inv = rsqrtf(var + 1e-5f);
#pragma unroll
            for (int nt = 0; nt < 4; nt++) {
                int col = wn * 32 + nt * 8 + t2;
                float2 gg = *(const float2*)(g + col);
                float2 bbv = *(const float2*)(b + col);
                float h0 = (acc[mt][nt][half * 2 + 0] - mu) * inv * gg.x + bbv.x;
                float h1 = (acc[mt][nt][half * 2 + 1] - mu) * inv * gg.y + bbv.y;
                __half2 p = __floats2half2_rn(h0, h1);
                *(uint32_t*)(b0c + lrow * SMSB + col * 2) = *(const uint32_t*)&p;
            }
        }
    }
    CPA_WAIT(0);      // G1 done (W1h0 in B2)
    __syncthreads();  // xn visible

    // h0: t0 = silu(xn @ W1h0) -> B1 (per-mt quarters; low reg pressure)
#pragma unroll
    for (int mt = 0; mt < 4; mt++) {
        float acc1[4][4];
#pragma unroll
        for (int nt = 0; nt < 4; nt++)
#pragma unroll
            for (int j = 0; j < 4; j++) acc1[nt][j] = 0.0f;
        compute_mt(acc1, B0 + (wm * 64 + mt * 16) * SMSB, B2, wn, lane);
        int row0 = wm * 64 + mt * 16 + q;
#pragma unroll
        for (int nt = 0; nt < 4; nt++) {
            int col = wn * 32 + nt * 8 + t2;
#pragma unroll
            for (int half = 0; half < 2; half++) {
                float s0 = acc1[nt][half * 2 + 0];
                float s1 = acc1[nt][half * 2 + 1];
                s0 = s0 / (1.0f + expf(-s0));
                s1 = s1 / (1.0f + expf(-s1));
                __half2 p = __floats2half2_rn(s0, s1);
                *(uint32_t*)(b1c + (row0 + half * 8) * SMSB + col * 2) =
                    *(const uint32_t*)&p;
            }
        }
    }
    __syncthreads();  // t0 visible; B2 free

    // W2 chunk0 -> B2
    for (int i = tid; i < 2048; i += 256) {
        int n = i >> 4, j = i & 15;
        cpa16(B2 + n * SMSB + j * 16, W2 + (size_t)n * 528 + j * 16);
    }
    CPA_COMMIT();
    CPA_WAIT(0);
    __syncthreads();

    // acc += t0 @ W2c0 (x2-seeded accumulate)
#pragma unroll
    for (int mt = 0; mt < 4; mt++)
        compute_mt(acc[mt], B1 + (wm * 64 + mt * 16) * SMSB, B2, wn, lane);
    __syncthreads();  // B1, B2 free

    // W1 half1 -> B1
    for (int i = tid * 16; i < TILEB; i += 4096) cpa16(B1 + i, W1 + TILEB + i);
    CPA_COMMIT();
    CPA_WAIT(0);
    __syncthreads();

    // h1: t1 = silu(xn @ W1h1) -> B2
#pragma unroll
    for (int mt = 0; mt < 4; mt++) {
        float acc1[4][4];
#pragma unroll
        for (int nt = 0; nt < 4; nt++)
#pragma unroll
            for (int j = 0; j < 4; j++) acc1[nt][j] = 0.0f;
        compute_mt(acc1, B0 + (wm * 64 + mt * 16) * SMSB, B1, wn, lane);
        int row0 = wm * 64 + mt * 16 + q;
#pragma unroll
        for (int nt = 0; nt < 4; nt++) {
            int col = wn * 32 + nt * 8 + t2;
#pragma unroll
            for (int half = 0; half < 2; half++) {
                float s0 = acc1[nt][half * 2 + 0];
                float s1 = acc1[nt][half * 2 + 1];
                s0 = s0 / (1.0f + expf(-s0));
                s1 = s1 / (1.0f + expf(-s1));
                __half2 p = __floats2half2_rn(s0, s1);
                *(uint32_t*)(b2c + (row0 + half * 8) * SMSB + col * 2) =
                    *(const uint32_t*)&p;
            }
        }
    }
    __syncthreads();  // t1 visible; B0 (xn) dead, B1 free

    // W2 chunk1 -> B0
    for (int i = tid; i < 2048; i += 256) {
        int n = i >> 4, j = i & 15;
        cpa16(B0 + n * SMSB + j * 16, W2 + (size_t)n * 528 + 256 + j * 16);
    }
    CPA_COMMIT();
    CPA_WAIT(0);
    __syncthreads();

    // acc += t1 @ W2c1
#pragma unroll
    for (int mt = 0; mt < 4; mt++)
        compute_mt(acc[mt], B2 + (wm * 64 + mt * 16) * SMSB, B0, wn, lane);

    // epilogue: out = acc (x2 + FFN), single write
#pragma unroll
    for (int mt = 0; mt < 4; mt++) {
#pragma unroll
        for (int half = 0; half < 2; half++) {
            int grow = m0 + wm * 64 + mt * 16 + q + half * 8;
            if (grow >= M) continue;
#pragma unroll
            for (int nt = 0; nt < 4; nt++) {
                int col = wn * 32 + nt * 8 + t2;
                *(float2*)(out + (size_t)grow * 128 + col) =
                    make_float2(acc[mt][nt][half * 2 + 0], acc[mt][nt][half * 2 + 1]);
            }
        }
    }
}

// ====== weight prep: all 10 weights, fp16, one launch ======
__global__ void prep_all(const float* w0, const float* w1, const float* w2,
                         const float* w3, const float* w4, const float* w5,
                         const float* w6, const float* w7, const float* w8,
                         const float* w9, char* __restrict__ ib) {
    int y = blockIdx.y;
    const float* W;
    int K = 128, N = 128;
    switch (y) {
        case 0: W = w0; break;
        case 1: W = w1; break;
        case 2: W = w2; break;
        case 3: W = w3; break;
        case 4: W = w4; break;
        case 5: W = w5; break;
        case 6: W = w6; N = 256; break;
        case 7: W = w7; N = 256; break;
        case 8: W = w8; K = 256; break;
        default: W = w9; K = 256; break;
    }
    int idx = blockIdx.x * 256 + threadIdx.x;
    if (idx >= K * N) return;
    int k = idx / N, n = idx % N;
    size_t off = (size_t)y * 81920 + ((size_t)n * (K + 8) + k) * 2;
    *(unsigned short*)(ib + off) = __half_as_ushort(__float2half_rn(W[idx]));
}

__global__ void zero2_kernel(float* __restrict__ a, size_t na,
                             float* __restrict__ bz, size_t nb) {
    size_t i = (size_t)blockIdx.x * blockDim.x + threadIdx.x;
    size_t st = (size_t)gridDim.x * blockDim.x;
    for (size_t k = i; k < na; k += st) a[k] = 0.0f;
    for (size_t k = i; k < nb; k += st) bz[k] = 0.0f;
}

// ================= launch =================
extern "C" void kernel_launch(void* const* d_in, const int* in_sizes, int n_in,
                              void* d_out, int out_size) {
    const float* node = (const float*)d_in[0];
    const float* edge = (const float*)d_in[1];
    const int*   eidx = (const int*)d_in[2];
    const float* Wq = (const float*)d_in[3];
    const float* Wk = (const float*)d_in[4];
    const float* Wv = (const float*)d_in[5];
    const float* We = (const float*)d_in[6];
    const float* Wo_n = (const float*)d_in[7];
    const float* bo_n = (const float*)d_in[8];
    const float* Wo_e = (const float*)d_in[9];
    const float* bo_e = (const float*)d_in[10];
    const float* W1n = (const float*)d_in[11];
    const float* W2n = (const float*)d_in[12];
    const float* W1e = (const float*)d_in[13];
    const float* W2e = (const float*)d_in[14];
    const float* g1n = (const float*)d_in[15];
    const float* b1n = (const float*)d_in[16];
    const float* g1e = (const float*)d_in[17];
    const float* b1e = (const float*)d_in[18];
    const float* g2n = (const float*)d_in[19];
    const float* b2n = (const float*)d_in[20];
    const float* g2e = (const float*)d_in[21];
    const float* b2e = (const float*)d_in[22];

    const int N = in_sizes[0] / 128;
    const int E = in_sizes[1] / 128;
    float* out = (float*)d_out;

    __half *Q, *Kb, *Vb, *PE;
    float *wV, *z;
    char* wim;
    cudaGetSymbolAddress((void**)&Q, g_Q);
    cudaGetSymbolAddress((void**)&Kb, g_Kb);
    cudaGetSymbolAddress((void**)&Vb, g_Vb);
    cudaGetSymbolAddress((void**)&PE, g_PE);
    cudaGetSymbolAddress((void**)&wV, g_wV);
    cudaGetSymbolAddress((void**)&z, g_z);
    cudaGetSymbolAddress((void**)&wim, g_wimg);

    auto IM = [&](int i) { return wim + (size_t)i * 81920; };

    const int SMG = 3 * TILEB;           // 104448
    const int SMO = 3 * TILEB + 4096;    // 108544
    cudaFuncSetAttribute((const void*)proj_gemm_all, cudaFuncAttributeMaxDynamicSharedMemorySize, SMG);
    cudaFuncSetAttribute((const void*)out_ffn_all, cudaFuncAttributeMaxDynamicSharedMemorySize, SMO);

    const int TtN = (N + 127) / 128;
    const int TtE = (E + 127) / 128;

    // 0) weight images + accumulator zeroing
    prep_all<<<dim3(128, 10), 256>>>(Wq, Wk, Wv, We, Wo_n, Wo_e, W1n, W1e, W2n, W2e, wim);
    zero2_kernel<<<2048, 256>>>(wV, (size_t)N * 128, z, (size_t)N * 8);

    // 1) projections: node QKV 3-in-1 + edge PE, one launch
    proj_gemm_all<<<TtN + TtE, 512, SMG>>>(TtN, node, edge, g1n, b1n, g1e, b1e,
                                           wim, Q, Kb, Vb, PE, N, E);

    // 2) per-edge attention + aggregation
    edge_kernel<<<(E + 7) / 8, 256>>>(Q, Kb, Vb, PE, eidx, wV, z, E);

    // 3) fused output chains, x2 register-resident
    out_ffn_all<<<TtN + TtE, 256, SMO>>>(TtN, N, E, wV, z, PE,
                                         IM(4), IM(5), bo_n, bo_e, node, edge,
                                         IM(6), IM(7), IM(8), IM(9),
                                         g2n, b2n, g2e, b2e, out);
}